// round 13
// baseline (speedup 1.0000x reference)
#include <cuda_runtime.h>

#define BB   32
#define SS   1024
#define DD   512
#define D2   1024
#define D3   1536
#define VV   49000
#define VP   49152
#define VF   50000
#define NCB  25
#define KB6  12
#define JB6  4

__device__ __align__(16) float g_temp_t [D3 * BB];
__device__ __align__(16) float g_dpart  [4 * BB * D2];
__device__ __align__(16) float g_dec1   [BB * D2];
__device__ __align__(16) float g_scores [BB * SS];
__device__ __align__(16) float g_attn   [BB * SS];
__device__ __align__(16) float g_cp2    [1024 * D2];
__device__            float g_mb     [1024];
__device__            float g_sb     [1024];
__device__ __align__(16) float g_hpart  [KB6 * BB * DD];
__device__ __align__(16) float g_hidden [BB * DD];
__device__            float g_pgen  [BB];
__device__            float g_pgen_acc[BB];
__device__ __align__(16) float g_lpart [2 * BB * VP];
__device__            float g_sumtot[BB];
__device__            int   g_ctr_d  [128];
__device__            int   g_ctr_dec1;
__device__            int   g_ctr_c2 [BB];
__device__            int   g_ctr_cb [BB];
__device__            int   g_ctr_v  [BB];
__device__            int   g_ctr_h  [JB6];
__device__            int   g_ctr_l  [24];
__device__            int   g_hready;

__device__ __forceinline__ float fast_tanh(float x) {
    float y;
    asm("tanh.approx.f32 %0, %1;" : "=f"(y) : "f"(x));
    return y;
}

// ===========================================================================
// A: dec1 split-K (bids 0..511) + score/pctx (512..1535) + combiners (1536..1663)
// ===========================================================================
__global__ void __launch_bounds__(256, 6)
kA_all(const float* __restrict__ h, const float* __restrict__ c,
       const float* __restrict__ dec_output,
       const float* __restrict__ W, const float* __restrict__ bias,
       const float4* __restrict__ enc1, const float4* __restrict__ wattn,
       const float4* __restrict__ enc, const int* __restrict__ src,
       float* __restrict__ out_attn,
       const float* __restrict__ bn_m, const float* __restrict__ bn_v,
       const float* __restrict__ gam,  const float* __restrict__ bet,
       const float* __restrict__ Wp,   const float* __restrict__ bp,
       const float* __restrict__ dinp, float* __restrict__ out_ctx) {
    __shared__ __align__(16) float abuf[5152];
    __shared__ float sscore[32];
    __shared__ float sp[32];
    __shared__ float sred[8];
    __shared__ int slast;
    int t = threadIdx.x;
    int bid = blockIdx.x;

    if (bid < 512) {
        // ---- dec1 split-K: jb = bid>>2 (8 j), ks = bid&3 (256 k) ----
        if (bid == 0) {
            // zero counters consumed by kC/kD this replay (kernel boundary orders)
            if (t < BB) { g_ctr_v[t] = 0; g_sumtot[t] = 0.f; }
            if (t >= 32 && t < 56) g_ctr_l[t - 32] = 0;
            if (t == 56) g_hready = 0;
            if (t >= 64 && t < 64 + JB6) g_ctr_h[t - 64] = 0;
        }
        int jb = bid >> 2, ks = bid & 3;
        int j0 = jb * 8;
        float* sdec = abuf;            // [32][129]
        float* sW   = abuf + 4128;     // [8][128]
        int jj = t >> 5, b = t & 31;
        if (bid < 128 && t < 128) {
            int i = bid * 128 + t;
            int k = i >> 5, bb = i & 31;
            g_temp_t[i] = dec_output[bb * DD + k];
        }
        float a0 = 0.f, a1 = 0.f, a2 = 0.f, a3 = 0.f;
#pragma unroll
        for (int ch = 0; ch < 2; ch++) {
            int k0 = ks * 256 + ch * 128;
            __syncthreads();
#pragma unroll
            for (int m = 0; m < 16; m++) {
                int e = m * 256 + t;
                int bb = e >> 7, kk = e & 127;
                int kg = k0 + kk;
                sdec[bb * 129 + kk] = (kg < DD) ? h[bb * DD + kg] : c[bb * DD + kg - DD];
            }
#pragma unroll
            for (int m = 0; m < 4; m++) {
                int e = m * 256 + t;
                int jx = e >> 7, kk = e & 127;
                sW[jx * 128 + kk] = W[(j0 + jx) * D2 + k0 + kk];
            }
            __syncthreads();
#pragma unroll
            for (int kk = 0; kk < 128; kk += 4) {
                a0 += sW[jj * 128 + kk + 0] * sdec[b * 129 + kk + 0];
                a1 += sW[jj * 128 + kk + 1] * sdec[b * 129 + kk + 1];
                a2 += sW[jj * 128 + kk + 2] * sdec[b * 129 + kk + 2];
                a3 += sW[jj * 128 + kk + 3] * sdec[b * 129 + kk + 3];
            }
        }
        g_dpart[(ks * 32 + b) * D2 + j0 + jj] = (a0 + a1) + (a2 + a3);
        __syncthreads();
        if (t == 0) {
            __threadfence();
            int old = atomicAdd(&g_ctr_d[jb], 1);
            slast = (old == 3);
        }
        __syncthreads();
        if (!slast) return;
        __threadfence();
        float tot = bias[j0 + jj];
#pragma unroll
        for (int ks2 = 0; ks2 < 4; ks2++)
            tot += __ldcg(&g_dpart[(ks2 * 32 + b) * D2 + j0 + jj]);
        g_dec1[b * D2 + j0 + jj] = tot;
        __threadfence();
        __syncthreads();
        if (t == 0) atomicAdd(&g_ctr_dec1, 1);
        return;
    }

    if (bid < 1536) {
        // ---- score (row-interleaved MLP) + local softmax + partial context ----
        float4* sd1 = (float4*)abuf;          // [256]
        float4* swa = ((float4*)abuf) + 256;  // [256]
        int idx = bid - 512;                  // 0..1023
        int b = idx >> 5, sb32 = idx & 31;
        int row0 = b * SS + sb32 * 32;
        swa[t] = wattn[t];
        if (t == 0) {
            while (*(volatile int*)&g_ctr_dec1 < 128) __nanosleep(64);
        }
        __syncthreads();
        __threadfence();
        sd1[t] = __ldcg(((const float4*)g_dec1) + b * 256 + t);
        __syncthreads();
        int lane = t & 31, w = t >> 5;
        const float4* er = enc1 + (size_t)(row0 + w * 4) * 256 + lane;
        float ac0 = 0.f, ac1 = 0.f, ac2 = 0.f, ac3 = 0.f;
#pragma unroll
        for (int i = 0; i < 8; i++) {
            int cidx = i * 32 + lane;
            float4 e0 = er[i * 32];
            float4 e1 = er[256 + i * 32];
            float4 e2 = er[512 + i * 32];
            float4 e3 = er[768 + i * 32];
            float4 dd = sd1[cidx];
            float4 wa = swa[cidx];
            ac0 += fast_tanh(e0.x + dd.x) * wa.x + fast_tanh(e0.y + dd.y) * wa.y
                 + fast_tanh(e0.z + dd.z) * wa.z + fast_tanh(e0.w + dd.w) * wa.w;
            ac1 += fast_tanh(e1.x + dd.x) * wa.x + fast_tanh(e1.y + dd.y) * wa.y
                 + fast_tanh(e1.z + dd.z) * wa.z + fast_tanh(e1.w + dd.w) * wa.w;
            ac2 += fast_tanh(e2.x + dd.x) * wa.x + fast_tanh(e2.y + dd.y) * wa.y
                 + fast_tanh(e2.z + dd.z) * wa.z + fast_tanh(e2.w + dd.w) * wa.w;
            ac3 += fast_tanh(e3.x + dd.x) * wa.x + fast_tanh(e3.y + dd.y) * wa.y
                 + fast_tanh(e3.z + dd.z) * wa.z + fast_tanh(e3.w + dd.w) * wa.w;
        }
#pragma unroll
        for (int o = 16; o; o >>= 1) {
            ac0 += __shfl_down_sync(0xffffffffu, ac0, o);
            ac1 += __shfl_down_sync(0xffffffffu, ac1, o);
            ac2 += __shfl_down_sync(0xffffffffu, ac2, o);
            ac3 += __shfl_down_sync(0xffffffffu, ac3, o);
        }
        if (!lane) {
            int lr = w * 4;
            sscore[lr + 0] = ac0; g_scores[row0 + lr + 0] = ac0;
            sscore[lr + 1] = ac1; g_scores[row0 + lr + 1] = ac1;
            sscore[lr + 2] = ac2; g_scores[row0 + lr + 2] = ac2;
            sscore[lr + 3] = ac3; g_scores[row0 + lr + 3] = ac3;
        }
        __syncthreads();
        float m = sscore[0];
#pragma unroll
        for (int i = 1; i < 32; i++) m = fmaxf(m, sscore[i]);
        if (t < 32) {
            int sv = src[row0 + t];
            sp[t] = (sv != 0) ? __expf(sscore[t] - m) : 0.f;
        }
        __syncthreads();
        if (t == 0) {
            float sum = 0.f;
#pragma unroll
            for (int i = 0; i < 32; i++) sum += sp[i];
            g_mb[idx] = m;
            g_sb[idx] = sum;
        }
        float4 acc4 = make_float4(0.f, 0.f, 0.f, 0.f);
        const float4* ebase = enc + (size_t)row0 * 256 + t;
#pragma unroll 8
        for (int i = 0; i < 32; i++) {
            float pi = sp[i];
            float4 ee = ebase[(size_t)i * 256];
            acc4.x += pi * ee.x; acc4.y += pi * ee.y;
            acc4.z += pi * ee.z; acc4.w += pi * ee.w;
        }
        ((float4*)g_cp2)[idx * 256 + t] = acc4;
        __threadfence();
        __syncthreads();
        if (t == 0) atomicAdd(&g_ctr_c2[b], 1);
        return;
    }

    // ---- combiners: 4 per b, 256 dims each ----
    {
        int idx = bid - 1536;       // 0..127
        int b = idx >> 2, ch = idx & 3;
        float* sw2 = abuf;          // [32]
        float* smv = abuf + 32;     // [32]
        float* ssv = abuf + 64;     // [32]
        if (t == 0) {
            while (*(volatile int*)&g_ctr_c2[b] < 32) __nanosleep(64);
        }
        __syncthreads();
        __threadfence();
        if (t < 32) {
            smv[t] = __ldcg(&g_mb[b * 32 + t]);
            ssv[t] = __ldcg(&g_sb[b * 32 + t]);
        }
        __syncthreads();
        float M = smv[0];
#pragma unroll
        for (int i = 1; i < 32; i++) M = fmaxf(M, smv[i]);
        if (t < 32) sw2[t] = __expf(smv[t] - M);
        __syncthreads();
        float Z = 0.f;
#pragma unroll
        for (int i = 0; i < 32; i++) Z += sw2[i] * ssv[i];
        float invZ = 1.f / Z;
        int d = ch * 256 + t;
        float acA = 0.f, acB = 0.f;
#pragma unroll 8
        for (int i = 0; i < 32; i += 2) {
            acA += sw2[i]     * __ldcg(&g_cp2[(size_t)(b * 32 + i)     * D2 + d]);
            acB += sw2[i + 1] * __ldcg(&g_cp2[(size_t)(b * 32 + i + 1) * D2 + d]);
        }
        float ctxv = (acA + acB) * invZ;
        float cx = (ctxv - bn_m[d]) * rsqrtf(bn_v[d] + 1e-5f) * gam[d] + bet[d];
        out_ctx[b * D2 + d] = cx;
        g_temp_t[(DD + d) * 32 + b] = cx;
        float pg = Wp[d] * cx;
        if (ch == 0) {
#pragma unroll
            for (int dd = 0; dd < 4; dd++) {
                int d2 = dd * 256 + t;
                float dop = (d2 < DD) ? h[b * DD + d2] : c[b * DD + d2 - DD];
                pg += Wp[D2 + d2] * dop;
            }
#pragma unroll
            for (int dd = 0; dd < 2; dd++) {
                int d2 = dd * 256 + t;
                pg += Wp[2048 + d2] * dinp[b * DD + d2];
            }
            float4 sc4 = ((const float4*)g_scores)[b * 256 + t];
            int4   id4 = ((const int4*)src)[b * 256 + t];
            float4 a4;
            a4.x = (id4.x != 0) ? __expf(sc4.x - M) * invZ : 0.f;
            a4.y = (id4.y != 0) ? __expf(sc4.y - M) * invZ : 0.f;
            a4.z = (id4.z != 0) ? __expf(sc4.z - M) * invZ : 0.f;
            a4.w = (id4.w != 0) ? __expf(sc4.w - M) * invZ : 0.f;
            ((float4*)g_attn)[b * 256 + t] = a4;
            ((float4*)out_attn)[b * 256 + t] = a4;
        }
#pragma unroll
        for (int o = 16; o; o >>= 1) pg += __shfl_down_sync(0xffffffffu, pg, o);
        if (!(t & 31)) sred[t >> 5] = pg;
        __syncthreads();
        if (t == 0) {
            float tot = 0.f;
#pragma unroll
            for (int i = 0; i < 8; i++) tot += sred[i];
            atomicAdd(&g_pgen_acc[b], tot);
            __threadfence();
            int old = atomicAdd(&g_ctr_cb[b], 1);
            slast = (old == 3);
        }
        __syncthreads();
        if (slast && t == 0) {
            __threadfence();
            float tot = __ldcg(&g_pgen_acc[b]) + bp[0];
            g_pgen[b] = 1.f / (1.f + __expf(-tot));
        }
    }
}

// ===========================================================================
// C: k6 hidden GEMM (bids 0..47) + k8a vocab logits (48..431)
//    + kD exp/scatter/finalize (432..1231, b-major rows for deadlock-safety)
// ===========================================================================
#define XS6  68
#define WSTR 20
__global__ void __launch_bounds__(256, 2)
kC_all(const float* __restrict__ Wv1, const float* __restrict__ bv1,
       const float* __restrict__ Wv2, const float* __restrict__ bv2,
       float* __restrict__ dout, const int* __restrict__ src) {
    __shared__ __align__(16) float cbuf[10880];
    __shared__ int slast;
    int t = threadIdx.x;
    int bid = blockIdx.x;

    if (bid < 48) {
        if (bid == 0) {
            // zero counters consumed by next replay's kA (this replay's kA is done)
            if (t < 128) g_ctr_d[t] = 0;
            else if (t < 160) g_ctr_c2[t - 128] = 0;
            else if (t < 192) g_ctr_cb[t - 160] = 0;
            else if (t < 224) g_pgen_acc[t - 192] = 0.f;
            else if (t == 224) g_ctr_dec1 = 0;
        }
        float* sW = cbuf;
        float* sX = cbuf + 128 * XS6;
        int tj = t & 63, tb = t >> 6;
        int jb = bid & 3, kb = bid >> 2;
        int j0 = jb * 128;
        unsigned long long acc2[2][8];
#pragma unroll
        for (int jr = 0; jr < 2; jr++)
#pragma unroll
            for (int bj = 0; bj < 8; bj++) acc2[jr][bj] = 0ull;
#pragma unroll
        for (int sub = 0; sub < 2; sub++) {
            int k0s = kb * 128 + sub * 64;
            __syncthreads();
#pragma unroll
            for (int li = 0; li < 8; li++) {
                int flat = li * 256 + t;
                int row = flat >> 4, kc = flat & 15;
                float4 f = *(const float4*)(Wv1 + (size_t)(j0 + row) * D3 + k0s + kc * 4);
                *(float4*)(sW + row * XS6 + kc * 4) = f;
            }
#pragma unroll
            for (int li = 0; li < 2; li++) {
                int flat = li * 256 + t;
                int kk = flat >> 3, bq = flat & 7;
                float4 f = ((const float4*)g_temp_t)[(size_t)(k0s + kk) * 8 + bq];
                sX[(bq * 4 + 0) * XS6 + kk] = f.x;
                sX[(bq * 4 + 1) * XS6 + kk] = f.y;
                sX[(bq * 4 + 2) * XS6 + kk] = f.z;
                sX[(bq * 4 + 3) * XS6 + kk] = f.w;
            }
            __syncthreads();
#pragma unroll
            for (int kq = 0; kq < 16; kq++) {
                ulonglong2 xv[8];
#pragma unroll
                for (int bj = 0; bj < 8; bj++)
                    xv[bj] = *(const ulonglong2*)(sX + (tb * 8 + bj) * XS6 + kq * 4);
#pragma unroll
                for (int jr = 0; jr < 2; jr++) {
                    ulonglong2 wv = *(const ulonglong2*)(sW + (jr * 64 + tj) * XS6 + kq * 4);
#pragma unroll
                    for (int bj = 0; bj < 8; bj++) {
                        asm("fma.rn.f32x2 %0, %1, %2, %0;"
                            : "+l"(acc2[jr][bj]) : "l"(wv.x), "l"(xv[bj].x));
                        asm("fma.rn.f32x2 %0, %1, %2, %0;"
                            : "+l"(acc2[jr][bj]) : "l"(wv.y), "l"(xv[bj].y));
                    }
                }
            }
        }
#pragma unroll
        for (int jr = 0; jr < 2; jr++)
#pragma unroll
            for (int bj = 0; bj < 8; bj++) {
                unsigned long long a = acc2[jr][bj];
                float v = __uint_as_float((unsigned)(a & 0xffffffffu)) +
                          __uint_as_float((unsigned)(a >> 32));
                g_hpart[((size_t)kb * 32 + tb * 8 + bj) * DD + j0 + jr * 64 + tj] = v;
            }
        __syncthreads();
        if (t == 0) {
            __threadfence();
            int old = atomicAdd(&g_ctr_h[jb], 1);
            slast = (old == KB6 - 1);
        }
        __syncthreads();
        if (!slast) return;
        __threadfence();
#pragma unroll
        for (int li = 0; li < 4; li++) {
            int flat = li * 256 + t;
            int b = flat >> 5, jq = flat & 31;
            float4 sum = *(const float4*)(bv1 + j0 + jq * 4);
#pragma unroll
            for (int p = 0; p < KB6; p++) {
                float4 v = __ldcg((const float4*)(g_hpart + ((size_t)p * 32 + b) * DD + j0 + jq * 4));
                sum.x += v.x; sum.y += v.y; sum.z += v.z; sum.w += v.w;
            }
            *(float4*)(g_hidden + (size_t)b * DD + j0 + jq * 4) = sum;
        }
        __threadfence();
        __syncthreads();
        if (t == 0) atomicAdd(&g_hready, 1);
        return;
    }

    if (bid < 432) {
        // ---- k8a vocab logits ----
        float* Ws = cbuf;
        float* Hs = cbuf + 256 * WSTR;
        int idx = bid - 48;
        int tv = t & 63, tb = t >> 6;
        int v0 = (idx % 192) * 256;
        int ks = idx / 192;
        int kbase = ks * 256;

        unsigned long long acc2[4][8];
#pragma unroll
        for (int j = 0; j < 4; j++)
#pragma unroll
            for (int bj = 0; bj < 8; bj++) acc2[j][bj] = 0ull;

        float4 wreg[4];
        float  hreg0, hreg1;
        {
            int k0 = kbase;
#pragma unroll
            for (int li = 0; li < 4; li++) {
                int flat = li * 256 + t;
                int v = flat >> 2, kq = flat & 3;
                int gv = v0 + v;
                wreg[li] = (gv < VV)
                    ? *(const float4*)(Wv2 + (size_t)gv * DD + k0 + kq * 4)
                    : make_float4(0.f, 0.f, 0.f, 0.f);
            }
#pragma unroll
            for (int li = 0; li < 4; li++) {
                int flat = li * 256 + t;
                int v = flat >> 2, kq = flat & 3;
                *(float4*)(Ws + v * WSTR + kq * 4) = wreg[li];
            }
        }
        if (t == 0) {
            while (*(volatile int*)&g_hready < JB6) __nanosleep(64);
        }
        __syncthreads();
        __threadfence();
        {
            int k0 = kbase;
            hreg0 = __ldcg(&g_hidden[((t)       >> 4) * DD + k0 + ((t)       & 15)]);
            hreg1 = __ldcg(&g_hidden[((t + 256) >> 4) * DD + k0 + ((t + 256) & 15)]);
            Hs[t] = hreg0;
            Hs[t + 256] = hreg1;
        }
        __syncthreads();

        for (int tile = 0; tile < 16; tile++) {
            if (tile < 15) {
                int k0 = kbase + (tile + 1) * 16;
#pragma unroll
                for (int li = 0; li < 4; li++) {
                    int flat = li * 256 + t;
                    int v = flat >> 2, kq = flat & 3;
                    int gv = v0 + v;
                    wreg[li] = (gv < VV)
                        ? *(const float4*)(Wv2 + (size_t)gv * DD + k0 + kq * 4)
                        : make_float4(0.f, 0.f, 0.f, 0.f);
                }
                hreg0 = g_hidden[((t)       >> 4) * DD + k0 + ((t)       & 15)];
                hreg1 = g_hidden[((t + 256) >> 4) * DD + k0 + ((t + 256) & 15)];
            }
#pragma unroll
            for (int kq = 0; kq < 4; kq++) {
                ulonglong2 h2[8];
#pragma unroll
                for (int bj = 0; bj < 8; bj++)
                    h2[bj] = *(const ulonglong2*)(Hs + (tb * 8 + bj) * 16 + kq * 4);
#pragma unroll
                for (int j = 0; j < 4; j++) {
                    ulonglong2 w2 = *(const ulonglong2*)(Ws + (tv + 64 * j) * WSTR + kq * 4);
#pragma unroll
                    for (int bj = 0; bj < 8; bj++) {
                        asm("fma.rn.f32x2 %0, %1, %2, %0;"
                            : "+l"(acc2[j][bj]) : "l"(w2.x), "l"(h2[bj].x));
                        asm("fma.rn.f32x2 %0, %1, %2, %0;"
                            : "+l"(acc2[j][bj]) : "l"(w2.y), "l"(h2[bj].y));
                    }
                }
            }
            if (tile < 15) {
                __syncthreads();
#pragma unroll
                for (int li = 0; li < 4; li++) {
                    int flat = li * 256 + t;
                    int v = flat >> 2, kq = flat & 3;
                    *(float4*)(Ws + v * WSTR + kq * 4) = wreg[li];
                }
                Hs[t] = hreg0;
                Hs[t + 256] = hreg1;
                __syncthreads();
            }
        }
        float accf[4][8];
#pragma unroll
        for (int j = 0; j < 4; j++)
#pragma unroll
            for (int bj = 0; bj < 8; bj++) {
                unsigned long long a = acc2[j][bj];
                accf[j][bj] = __uint_as_float((unsigned)(a & 0xffffffffu)) +
                              __uint_as_float((unsigned)(a >> 32));
            }
#pragma unroll
        for (int p = 0; p < 2; p++) {
            __syncthreads();
            if ((tb >> 1) == p) {
#pragma unroll
                for (int j = 0; j < 4; j++)
#pragma unroll
                    for (int bj = 0; bj < 8; bj++)
                        Ws[((tb & 1) * 8 + bj) * 256 + tv + 64 * j] = accf[j][bj];
            }
            __syncthreads();
#pragma unroll
            for (int i = 0; i < 4; i++) {
                int ii = i * 256 + t;
                int row = ii >> 6, col = ii & 63;
                *(float4*)(g_lpart + ((size_t)(ks * 32 + p * 16 + row) * VP + v0 + col * 4)) =
                    *(const float4*)(Ws + row * 256 + col * 4);
            }
        }
        __threadfence();
        __syncthreads();
        if (t == 0) atomicAdd(&g_ctr_l[(idx % 192) >> 3], 1);
        return;
    }

    // ---- kD part: bid = 432 + b*25 + cb (contiguous rows → deadlock-safe) ----
    {
        int idx2 = bid - 432;
        int b = idx2 / 25, cb = idx2 - b * 25;
        float* ssc = cbuf;            // [2048]
        float* smr = cbuf + 2048;     // [8]
        int base = cb * 2048;
        // gate on this chunk's logit region (16 producer blocks)
        if (cb < 24) {
            if (t == 0) {
                while (*(volatile int*)&g_ctr_l[cb] < 16) __nanosleep(64);
            }
        }
        __syncthreads();
        __threadfence();
        float pg = g_pgen[b];
        float ev[8];
        float sum = 0.f;
#pragma unroll
        for (int it = 0; it < 8; it++) {
            int v = base + it * 256 + t;
            float e = 0.f;
            if (v < VV) {
                float l = __ldcg(&g_lpart[(size_t)b * VP + v]) +
                          __ldcg(&g_lpart[(size_t)(32 + b) * VP + v]) + bv2[v];
                e = __expf(l);
                sum += e;
            }
            ev[it] = e;
        }
#pragma unroll
        for (int o = 16; o; o >>= 1) sum += __shfl_down_sync(0xffffffffu, sum, o);
        if (!(t & 31)) smr[t >> 5] = sum;
        __syncthreads();
        if (t == 0) {
            float tot = 0.f;
#pragma unroll
            for (int i = 0; i < 8; i++) tot += smr[i];
            atomicAdd(&g_sumtot[b], tot);
            __threadfence();
            atomicAdd(&g_ctr_v[b], 1);
        }
#pragma unroll
        for (int i = 0; i < 8; i++) ssc[i * 256 + t] = 0.f;
        __syncthreads();
#pragma unroll
        for (int i = 0; i < 4; i++) {
            int si = i * 256 + t;
            int idx = src[b * SS + si];
            int off = idx - base;
            if ((unsigned)off < 2048u)
                atomicAdd(&ssc[off], g_attn[b * SS + si]);
        }
        __syncthreads();
        if (t == 0) {
            while (*(volatile int*)&g_ctr_v[b] < NCB) __nanosleep(32);
        }
        __syncthreads();
        __threadfence();
        float s  = __ldcg(&g_sumtot[b]);
        float sc = pg / s;
        float f  = 1.f - pg;
#pragma unroll
        for (int it = 0; it < 8; it++) {
            int v = base + it * 256 + t;
            if (v < VF) {
                float p = ev[it] * sc + f * ssc[it * 256 + t];
                if (p == 0.f) p = 1e-12f;
                dout[(size_t)b * VF + v] = p;
            }
        }
    }
}

extern "C" void kernel_launch(void* const* d_in, const int* in_sizes, int n_in,
                              void* d_out, int out_size) {
    const float* dec_output = (const float*)d_in[0];
    const float* hh         = (const float*)d_in[1];
    const float* cc         = (const float*)d_in[2];
    const float* dinp       = (const float*)d_in[3];
    const float* enc        = (const float*)d_in[4];
    const float* enc1       = (const float*)d_in[5];
    const int*   src        = (const int*)  d_in[6];
    const float* W_dec      = (const float*)d_in[7];
    const float* b_dec      = (const float*)d_in[8];
    const float* w_attn     = (const float*)d_in[9];
    const float* W_v1       = (const float*)d_in[10];
    const float* b_v1       = (const float*)d_in[11];
    const float* W_v2       = (const float*)d_in[12];
    const float* b_v2       = (const float*)d_in[13];
    const float* W_p        = (const float*)d_in[14];
    const float* b_p        = (const float*)d_in[15];
    const float* gam        = (const float*)d_in[16];
    const float* bet        = (const float*)d_in[17];
    const float* bn_m       = (const float*)d_in[18];
    const float* bn_v       = (const float*)d_in[19];

    float* dout     = (float*)d_out;
    float* out_attn = dout + BB * VF;
    float* out_ctx  = out_attn + BB * SS;

    kA_all<<<1664, 256>>>(hh, cc, dec_output, W_dec, b_dec,
                          (const float4*)enc1, (const float4*)w_attn,
                          (const float4*)enc, src, out_attn,
                          bn_m, bn_v, gam, bet, W_p, b_p, dinp, out_ctx);
    kC_all<<<1232, 256>>>(W_v1, b_v1, W_v2, b_v2, dout, src);
}

// round 14
// speedup vs baseline: 1.0309x; 1.0309x over previous
#include <cuda_runtime.h>

#define BB   32
#define SS   1024
#define DD   512
#define D2   1024
#define D3   1536
#define VV   49000
#define VP   49152
#define VF   50000
#define NCB  25
#define KB6  12
#define JB6  4

__device__ __align__(16) float g_temp_t [D3 * BB];
__device__ __align__(16) float g_dpart  [4 * BB * D2];
__device__ __align__(16) float g_dec1   [BB * D2];
__device__ __align__(16) float g_scores [BB * SS];
__device__ __align__(16) float g_attn   [BB * SS];
__device__ __align__(16) float g_cp2    [1024 * D2];
__device__            float g_mb     [1024];
__device__            float g_sb     [1024];
__device__ __align__(16) float g_hpart  [KB6 * BB * DD];
__device__ __align__(16) float g_hidden [BB * DD];
__device__            float g_pgen  [BB];
__device__            float g_pgen_acc[BB];
__device__ __align__(16) float g_lpart [2 * BB * VP];
__device__            float g_sumtot[BB];
__device__            int   g_ctr_d  [128];
__device__            int   g_ctr_dec1;
__device__            int   g_ctr_c2 [BB];
__device__            int   g_ctr_cb [BB];
__device__            int   g_ctr_v  [BB];
__device__            int   g_ctr_h  [JB6];
__device__            int   g_hready;

__device__ __forceinline__ float fast_tanh(float x) {
    float y;
    asm("tanh.approx.f32 %0, %1;" : "=f"(y) : "f"(x));
    return y;
}

// ===========================================================================
// A: dec1 split-K (bids 0..511) + score/pctx (512..1535) + combiners (1536..1663)
// ===========================================================================
__global__ void __launch_bounds__(256, 6)
kA_all(const float* __restrict__ h, const float* __restrict__ c,
       const float* __restrict__ dec_output,
       const float* __restrict__ W, const float* __restrict__ bias,
       const float4* __restrict__ enc1, const float4* __restrict__ wattn,
       const float4* __restrict__ enc, const int* __restrict__ src,
       float* __restrict__ out_attn,
       const float* __restrict__ bn_m, const float* __restrict__ bn_v,
       const float* __restrict__ gam,  const float* __restrict__ bet,
       const float* __restrict__ Wp,   const float* __restrict__ bp,
       const float* __restrict__ dinp, float* __restrict__ out_ctx) {
    __shared__ __align__(16) float abuf[5152];
    __shared__ float sscore[32];
    __shared__ float sp[32];
    __shared__ float sred[8];
    __shared__ int slast;
    int t = threadIdx.x;
    int bid = blockIdx.x;

    if (bid < 512) {
        // ---- dec1 split-K: jb = bid>>2 (8 j), ks = bid&3 (256 k) ----
        int jb = bid >> 2, ks = bid & 3;
        int j0 = jb * 8;
        float* sdec = abuf;            // [32][129]
        float* sW   = abuf + 4128;     // [8][128]
        int jj = t >> 5, b = t & 31;
        if (bid < 128 && t < 128) {
            int i = bid * 128 + t;
            int k = i >> 5, bb = i & 31;
            g_temp_t[i] = dec_output[bb * DD + k];
        }
        float a0 = 0.f, a1 = 0.f, a2 = 0.f, a3 = 0.f;
#pragma unroll
        for (int ch = 0; ch < 2; ch++) {
            int k0 = ks * 256 + ch * 128;
            __syncthreads();
#pragma unroll
            for (int m = 0; m < 16; m++) {
                int e = m * 256 + t;
                int bb = e >> 7, kk = e & 127;
                int kg = k0 + kk;
                sdec[bb * 129 + kk] = (kg < DD) ? h[bb * DD + kg] : c[bb * DD + kg - DD];
            }
#pragma unroll
            for (int m = 0; m < 4; m++) {
                int e = m * 256 + t;
                int jx = e >> 7, kk = e & 127;
                sW[jx * 128 + kk] = W[(j0 + jx) * D2 + k0 + kk];
            }
            __syncthreads();
#pragma unroll
            for (int kk = 0; kk < 128; kk += 4) {
                a0 += sW[jj * 128 + kk + 0] * sdec[b * 129 + kk + 0];
                a1 += sW[jj * 128 + kk + 1] * sdec[b * 129 + kk + 1];
                a2 += sW[jj * 128 + kk + 2] * sdec[b * 129 + kk + 2];
                a3 += sW[jj * 128 + kk + 3] * sdec[b * 129 + kk + 3];
            }
        }
        g_dpart[(ks * 32 + b) * D2 + j0 + jj] = (a0 + a1) + (a2 + a3);
        __syncthreads();
        if (t == 0) {
            __threadfence();
            int old = atomicAdd(&g_ctr_d[jb], 1);
            slast = (old == 3);
        }
        __syncthreads();
        if (!slast) return;
        __threadfence();
        float tot = bias[j0 + jj];
#pragma unroll
        for (int ks2 = 0; ks2 < 4; ks2++)
            tot += __ldcg(&g_dpart[(ks2 * 32 + b) * D2 + j0 + jj]);
        g_dec1[b * D2 + j0 + jj] = tot;
        __threadfence();
        __syncthreads();
        if (t == 0) atomicAdd(&g_ctr_dec1, 1);
        return;
    }

    if (bid < 1536) {
        // ---- score (row-interleaved MLP) + local softmax + partial context ----
        float4* sd1 = (float4*)abuf;          // [256]
        float4* swa = ((float4*)abuf) + 256;  // [256]
        int idx = bid - 512;                  // 0..1023
        int b = idx >> 5, sb32 = idx & 31;
        int row0 = b * SS + sb32 * 32;
        swa[t] = wattn[t];
        if (t == 0) {
            while (*(volatile int*)&g_ctr_dec1 < 128) __nanosleep(64);
        }
        __syncthreads();
        __threadfence();
        sd1[t] = __ldcg(((const float4*)g_dec1) + b * 256 + t);
        __syncthreads();
        int lane = t & 31, w = t >> 5;
        const float4* er = enc1 + (size_t)(row0 + w * 4) * 256 + lane;
        float ac0 = 0.f, ac1 = 0.f, ac2 = 0.f, ac3 = 0.f;
#pragma unroll
        for (int i = 0; i < 8; i++) {
            int cidx = i * 32 + lane;
            float4 e0 = er[i * 32];
            float4 e1 = er[256 + i * 32];
            float4 e2 = er[512 + i * 32];
            float4 e3 = er[768 + i * 32];
            float4 dd = sd1[cidx];
            float4 wa = swa[cidx];
            ac0 += fast_tanh(e0.x + dd.x) * wa.x + fast_tanh(e0.y + dd.y) * wa.y
                 + fast_tanh(e0.z + dd.z) * wa.z + fast_tanh(e0.w + dd.w) * wa.w;
            ac1 += fast_tanh(e1.x + dd.x) * wa.x + fast_tanh(e1.y + dd.y) * wa.y
                 + fast_tanh(e1.z + dd.z) * wa.z + fast_tanh(e1.w + dd.w) * wa.w;
            ac2 += fast_tanh(e2.x + dd.x) * wa.x + fast_tanh(e2.y + dd.y) * wa.y
                 + fast_tanh(e2.z + dd.z) * wa.z + fast_tanh(e2.w + dd.w) * wa.w;
            ac3 += fast_tanh(e3.x + dd.x) * wa.x + fast_tanh(e3.y + dd.y) * wa.y
                 + fast_tanh(e3.z + dd.z) * wa.z + fast_tanh(e3.w + dd.w) * wa.w;
        }
#pragma unroll
        for (int o = 16; o; o >>= 1) {
            ac0 += __shfl_down_sync(0xffffffffu, ac0, o);
            ac1 += __shfl_down_sync(0xffffffffu, ac1, o);
            ac2 += __shfl_down_sync(0xffffffffu, ac2, o);
            ac3 += __shfl_down_sync(0xffffffffu, ac3, o);
        }
        if (!lane) {
            int lr = w * 4;
            sscore[lr + 0] = ac0; g_scores[row0 + lr + 0] = ac0;
            sscore[lr + 1] = ac1; g_scores[row0 + lr + 1] = ac1;
            sscore[lr + 2] = ac2; g_scores[row0 + lr + 2] = ac2;
            sscore[lr + 3] = ac3; g_scores[row0 + lr + 3] = ac3;
        }
        __syncthreads();
        float m = sscore[0];
#pragma unroll
        for (int i = 1; i < 32; i++) m = fmaxf(m, sscore[i]);
        if (t < 32) {
            int sv = src[row0 + t];
            sp[t] = (sv != 0) ? __expf(sscore[t] - m) : 0.f;
        }
        __syncthreads();
        if (t == 0) {
            float sum = 0.f;
#pragma unroll
            for (int i = 0; i < 32; i++) sum += sp[i];
            g_mb[idx] = m;
            g_sb[idx] = sum;
        }
        float4 acc4 = make_float4(0.f, 0.f, 0.f, 0.f);
        const float4* ebase = enc + (size_t)row0 * 256 + t;
#pragma unroll 8
        for (int i = 0; i < 32; i++) {
            float pi = sp[i];
            float4 ee = ebase[(size_t)i * 256];
            acc4.x += pi * ee.x; acc4.y += pi * ee.y;
            acc4.z += pi * ee.z; acc4.w += pi * ee.w;
        }
        ((float4*)g_cp2)[idx * 256 + t] = acc4;
        __threadfence();
        __syncthreads();
        if (t == 0) atomicAdd(&g_ctr_c2[b], 1);
        return;
    }

    // ---- combiners: 4 per b, 256 dims each ----
    {
        int idx = bid - 1536;       // 0..127
        int b = idx >> 2, ch = idx & 3;
        float* sw2 = abuf;          // [32]
        float* smv = abuf + 32;     // [32]
        float* ssv = abuf + 64;     // [32]
        if (t == 0) {
            while (*(volatile int*)&g_ctr_c2[b] < 32) __nanosleep(64);
        }
        __syncthreads();
        __threadfence();
        if (t < 32) {
            smv[t] = __ldcg(&g_mb[b * 32 + t]);
            ssv[t] = __ldcg(&g_sb[b * 32 + t]);
        }
        __syncthreads();
        float M = smv[0];
#pragma unroll
        for (int i = 1; i < 32; i++) M = fmaxf(M, smv[i]);
        if (t < 32) sw2[t] = __expf(smv[t] - M);
        __syncthreads();
        float Z = 0.f;
#pragma unroll
        for (int i = 0; i < 32; i++) Z += sw2[i] * ssv[i];
        float invZ = 1.f / Z;
        int d = ch * 256 + t;
        float acA = 0.f, acB = 0.f;
#pragma unroll 8
        for (int i = 0; i < 32; i += 2) {
            acA += sw2[i]     * __ldcg(&g_cp2[(size_t)(b * 32 + i)     * D2 + d]);
            acB += sw2[i + 1] * __ldcg(&g_cp2[(size_t)(b * 32 + i + 1) * D2 + d]);
        }
        float ctxv = (acA + acB) * invZ;
        float cx = (ctxv - bn_m[d]) * rsqrtf(bn_v[d] + 1e-5f) * gam[d] + bet[d];
        out_ctx[b * D2 + d] = cx;
        g_temp_t[(DD + d) * 32 + b] = cx;
        float pg = Wp[d] * cx;
        if (ch == 0) {
#pragma unroll
            for (int dd = 0; dd < 4; dd++) {
                int d2 = dd * 256 + t;
                float dop = (d2 < DD) ? h[b * DD + d2] : c[b * DD + d2 - DD];
                pg += Wp[D2 + d2] * dop;
            }
#pragma unroll
            for (int dd = 0; dd < 2; dd++) {
                int d2 = dd * 256 + t;
                pg += Wp[2048 + d2] * dinp[b * DD + d2];
            }
            float4 sc4 = ((const float4*)g_scores)[b * 256 + t];
            int4   id4 = ((const int4*)src)[b * 256 + t];
            float4 a4;
            a4.x = (id4.x != 0) ? __expf(sc4.x - M) * invZ : 0.f;
            a4.y = (id4.y != 0) ? __expf(sc4.y - M) * invZ : 0.f;
            a4.z = (id4.z != 0) ? __expf(sc4.z - M) * invZ : 0.f;
            a4.w = (id4.w != 0) ? __expf(sc4.w - M) * invZ : 0.f;
            ((float4*)g_attn)[b * 256 + t] = a4;
            ((float4*)out_attn)[b * 256 + t] = a4;
        }
#pragma unroll
        for (int o = 16; o; o >>= 1) pg += __shfl_down_sync(0xffffffffu, pg, o);
        if (!(t & 31)) sred[t >> 5] = pg;
        __syncthreads();
        if (t == 0) {
            float tot = 0.f;
#pragma unroll
            for (int i = 0; i < 8; i++) tot += sred[i];
            atomicAdd(&g_pgen_acc[b], tot);
            __threadfence();
            int old = atomicAdd(&g_ctr_cb[b], 1);
            slast = (old == 3);
        }
        __syncthreads();
        if (slast && t == 0) {
            __threadfence();
            float tot = __ldcg(&g_pgen_acc[b]) + bp[0];
            g_pgen[b] = 1.f / (1.f + __expf(-tot));
        }
    }
}

// ===========================================================================
// C: fused k6 (hidden GEMM, bids 0..47) + k8a (vocab logits, bids 48..431)
// ===========================================================================
#define XS6  68
#define WSTR 20
__global__ void __launch_bounds__(256, 2)
kC_hidden_logits(const float* __restrict__ Wv1, const float* __restrict__ bv1,
                 const float* __restrict__ Wv2) {
    __shared__ __align__(16) float cbuf[10880];
    __shared__ int slast;
    int t = threadIdx.x;
    int bid = blockIdx.x;

    if (bid < 48) {
        float* sW = cbuf;
        float* sX = cbuf + 128 * XS6;
        int tj = t & 63, tb = t >> 6;
        int jb = bid & 3, kb = bid >> 2;
        int j0 = jb * 128;
        unsigned long long acc2[2][8];
#pragma unroll
        for (int jr = 0; jr < 2; jr++)
#pragma unroll
            for (int bj = 0; bj < 8; bj++) acc2[jr][bj] = 0ull;
#pragma unroll
        for (int sub = 0; sub < 2; sub++) {
            int k0s = kb * 128 + sub * 64;
            __syncthreads();
#pragma unroll
            for (int li = 0; li < 8; li++) {
                int flat = li * 256 + t;
                int row = flat >> 4, kc = flat & 15;
                float4 f = *(const float4*)(Wv1 + (size_t)(j0 + row) * D3 + k0s + kc * 4);
                *(float4*)(sW + row * XS6 + kc * 4) = f;
            }
#pragma unroll
            for (int li = 0; li < 2; li++) {
                int flat = li * 256 + t;
                int kk = flat >> 3, bq = flat & 7;
                float4 f = ((const float4*)g_temp_t)[(size_t)(k0s + kk) * 8 + bq];
                sX[(bq * 4 + 0) * XS6 + kk] = f.x;
                sX[(bq * 4 + 1) * XS6 + kk] = f.y;
                sX[(bq * 4 + 2) * XS6 + kk] = f.z;
                sX[(bq * 4 + 3) * XS6 + kk] = f.w;
            }
            __syncthreads();
#pragma unroll
            for (int kq = 0; kq < 16; kq++) {
                ulonglong2 xv[8];
#pragma unroll
                for (int bj = 0; bj < 8; bj++)
                    xv[bj] = *(const ulonglong2*)(sX + (tb * 8 + bj) * XS6 + kq * 4);
#pragma unroll
                for (int jr = 0; jr < 2; jr++) {
                    ulonglong2 wv = *(const ulonglong2*)(sW + (jr * 64 + tj) * XS6 + kq * 4);
#pragma unroll
                    for (int bj = 0; bj < 8; bj++) {
                        asm("fma.rn.f32x2 %0, %1, %2, %0;"
                            : "+l"(acc2[jr][bj]) : "l"(wv.x), "l"(xv[bj].x));
                        asm("fma.rn.f32x2 %0, %1, %2, %0;"
                            : "+l"(acc2[jr][bj]) : "l"(wv.y), "l"(xv[bj].y));
                    }
                }
            }
        }
#pragma unroll
        for (int jr = 0; jr < 2; jr++)
#pragma unroll
            for (int bj = 0; bj < 8; bj++) {
                unsigned long long a = acc2[jr][bj];
                float v = __uint_as_float((unsigned)(a & 0xffffffffu)) +
                          __uint_as_float((unsigned)(a >> 32));
                g_hpart[((size_t)kb * 32 + tb * 8 + bj) * DD + j0 + jr * 64 + tj] = v;
            }
        __syncthreads();
        if (t == 0) {
            __threadfence();
            int old = atomicAdd(&g_ctr_h[jb], 1);
            slast = (old == KB6 - 1);
        }
        __syncthreads();
        if (!slast) return;
        __threadfence();
#pragma unroll
        for (int li = 0; li < 4; li++) {
            int flat = li * 256 + t;
            int b = flat >> 5, jq = flat & 31;
            float4 sum = *(const float4*)(bv1 + j0 + jq * 4);
#pragma unroll
            for (int p = 0; p < KB6; p++) {
                float4 v = __ldcg((const float4*)(g_hpart + ((size_t)p * 32 + b) * DD + j0 + jq * 4));
                sum.x += v.x; sum.y += v.y; sum.z += v.z; sum.w += v.w;
            }
            *(float4*)(g_hidden + (size_t)b * DD + j0 + jq * 4) = sum;
        }
        __threadfence();
        __syncthreads();
        if (t == 0) atomicAdd(&g_hready, 1);
        return;
    }

    // ---- k8a part ----
    float* Ws = cbuf;
    float* Hs = cbuf + 256 * WSTR;
    int idx = bid - 48;
    if (idx == 0 && t < BB) { g_sumtot[t] = 0.f; g_ctr_v[t] = 0; }
    int tv = t & 63, tb = t >> 6;
    int v0 = (idx % 192) * 256;
    int ks = idx / 192;
    int kbase = ks * 256;

    unsigned long long acc2[4][8];
#pragma unroll
    for (int j = 0; j < 4; j++)
#pragma unroll
        for (int bj = 0; bj < 8; bj++) acc2[j][bj] = 0ull;

    float4 wreg[4];
    float  hreg0, hreg1;
    {
        int k0 = kbase;
#pragma unroll
        for (int li = 0; li < 4; li++) {
            int flat = li * 256 + t;
            int v = flat >> 2, kq = flat & 3;
            int gv = v0 + v;
            wreg[li] = (gv < VV)
                ? *(const float4*)(Wv2 + (size_t)gv * DD + k0 + kq * 4)
                : make_float4(0.f, 0.f, 0.f, 0.f);
        }
#pragma unroll
        for (int li = 0; li < 4; li++) {
            int flat = li * 256 + t;
            int v = flat >> 2, kq = flat & 3;
            *(float4*)(Ws + v * WSTR + kq * 4) = wreg[li];
        }
    }
    if (t == 0) {
        while (*(volatile int*)&g_hready < JB6) __nanosleep(64);
    }
    __syncthreads();
    __threadfence();
    {
        int k0 = kbase;
        hreg0 = __ldcg(&g_hidden[((t)       >> 4) * DD + k0 + ((t)       & 15)]);
        hreg1 = __ldcg(&g_hidden[((t + 256) >> 4) * DD + k0 + ((t + 256) & 15)]);
        Hs[t] = hreg0;
        Hs[t + 256] = hreg1;
    }
    __syncthreads();

    for (int tile = 0; tile < 16; tile++) {
        if (tile < 15) {
            int k0 = kbase + (tile + 1) * 16;
#pragma unroll
            for (int li = 0; li < 4; li++) {
                int flat = li * 256 + t;
                int v = flat >> 2, kq = flat & 3;
                int gv = v0 + v;
                wreg[li] = (gv < VV)
                    ? *(const float4*)(Wv2 + (size_t)gv * DD + k0 + kq * 4)
                    : make_float4(0.f, 0.f, 0.f, 0.f);
            }
            hreg0 = g_hidden[((t)       >> 4) * DD + k0 + ((t)       & 15)];
            hreg1 = g_hidden[((t + 256) >> 4) * DD + k0 + ((t + 256) & 15)];
        }
#pragma unroll
        for (int kq = 0; kq < 4; kq++) {
            ulonglong2 h2[8];
#pragma unroll
            for (int bj = 0; bj < 8; bj++)
                h2[bj] = *(const ulonglong2*)(Hs + (tb * 8 + bj) * 16 + kq * 4);
#pragma unroll
            for (int j = 0; j < 4; j++) {
                ulonglong2 w2 = *(const ulonglong2*)(Ws + (tv + 64 * j) * WSTR + kq * 4);
#pragma unroll
                for (int bj = 0; bj < 8; bj++) {
                    asm("fma.rn.f32x2 %0, %1, %2, %0;"
                        : "+l"(acc2[j][bj]) : "l"(w2.x), "l"(h2[bj].x));
                    asm("fma.rn.f32x2 %0, %1, %2, %0;"
                        : "+l"(acc2[j][bj]) : "l"(w2.y), "l"(h2[bj].y));
                }
            }
        }
        if (tile < 15) {
            __syncthreads();
#pragma unroll
            for (int li = 0; li < 4; li++) {
                int flat = li * 256 + t;
                int v = flat >> 2, kq = flat & 3;
                *(float4*)(Ws + v * WSTR + kq * 4) = wreg[li];
            }
            Hs[t] = hreg0;
            Hs[t + 256] = hreg1;
            __syncthreads();
        }
    }
    float accf[4][8];
#pragma unroll
    for (int j = 0; j < 4; j++)
#pragma unroll
        for (int bj = 0; bj < 8; bj++) {
            unsigned long long a = acc2[j][bj];
            accf[j][bj] = __uint_as_float((unsigned)(a & 0xffffffffu)) +
                          __uint_as_float((unsigned)(a >> 32));
        }
#pragma unroll
    for (int p = 0; p < 2; p++) {
        __syncthreads();
        if ((tb >> 1) == p) {
#pragma unroll
            for (int j = 0; j < 4; j++)
#pragma unroll
                for (int bj = 0; bj < 8; bj++)
                    Ws[((tb & 1) * 8 + bj) * 256 + tv + 64 * j] = accf[j][bj];
        }
        __syncthreads();
#pragma unroll
        for (int i = 0; i < 4; i++) {
            int ii = i * 256 + t;
            int row = ii >> 6, col = ii & 63;
            *(float4*)(g_lpart + ((size_t)(ks * 32 + p * 16 + row) * VP + v0 + col * 4)) =
                *(const float4*)(Ws + row * 256 + col * 4);
        }
    }
}

// ===========================================================================
// D: exp (regs) + per-b sum; local smem scatter; spin on sum counter only;
//    single-pass combine + zero-fix. Zeroes kA counters for next replay.
// ===========================================================================
__global__ void kD_exp_final(const float* __restrict__ bv2, float* __restrict__ dout,
                             const int* __restrict__ src) {
    __shared__ float ssc[2048];
    __shared__ float sm[8];
    int b = blockIdx.x, cb = blockIdx.y, t = threadIdx.x;
    if (b == 0 && cb == 0) {
        if (t == 0) { g_ctr_dec1 = 0; g_hready = 0; }
        if (t < BB) { g_ctr_c2[t] = 0; g_ctr_cb[t] = 0; g_pgen_acc[t] = 0.f; }
        if (t < 128) g_ctr_d[t] = 0;
        if (t < JB6) g_ctr_h[t] = 0;
    }
    int base = cb * 2048;
    float pg = g_pgen[b];
    float ev[8];
    float sum = 0.f;
#pragma unroll
    for (int it = 0; it < 8; it++) {
        int v = base + it * 256 + t;
        float e = 0.f;
        if (v < VV) {
            float l = g_lpart[(size_t)b * VP + v] + g_lpart[(size_t)(32 + b) * VP + v] + bv2[v];
            e = __expf(l);
            sum += e;
        }
        ev[it] = e;
    }
#pragma unroll
    for (int o = 16; o; o >>= 1) sum += __shfl_down_sync(0xffffffffu, sum, o);
    if (!(t & 31)) sm[t >> 5] = sum;
    __syncthreads();
    if (t == 0) {
        float tot = 0.f;
#pragma unroll
        for (int i = 0; i < 8; i++) tot += sm[i];
        atomicAdd(&g_sumtot[b], tot);
        __threadfence();
        atomicAdd(&g_ctr_v[b], 1);
    }
#pragma unroll
    for (int i = 0; i < 8; i++) ssc[i * 256 + t] = 0.f;
    __syncthreads();
#pragma unroll
    for (int i = 0; i < 4; i++) {
        int si = i * 256 + t;
        int idx = src[b * SS + si];
        int off = idx - base;
        if ((unsigned)off < 2048u)
            atomicAdd(&ssc[off], g_attn[b * SS + si]);
    }
    __syncthreads();
    if (t == 0) {
        while (*(volatile int*)&g_ctr_v[b] < NCB) __nanosleep(32);
    }
    __syncthreads();
    __threadfence();
    float s  = __ldcg(&g_sumtot[b]);
    float sc = pg / s;
    float f  = 1.f - pg;
#pragma unroll
    for (int it = 0; it < 8; it++) {
        int v = base + it * 256 + t;
        if (v < VF) {
            float p = ev[it] * sc + f * ssc[it * 256 + t];
            if (p == 0.f) p = 1e-12f;
            dout[(size_t)b * VF + v] = p;
        }
    }
}

extern "C" void kernel_launch(void* const* d_in, const int* in_sizes, int n_in,
                              void* d_out, int out_size) {
    const float* dec_output = (const float*)d_in[0];
    const float* hh         = (const float*)d_in[1];
    const float* cc         = (const float*)d_in[2];
    const float* dinp       = (const float*)d_in[3];
    const float* enc        = (const float*)d_in[4];
    const float* enc1       = (const float*)d_in[5];
    const int*   src        = (const int*)  d_in[6];
    const float* W_dec      = (const float*)d_in[7];
    const float* b_dec      = (const float*)d_in[8];
    const float* w_attn     = (const float*)d_in[9];
    const float* W_v1       = (const float*)d_in[10];
    const float* b_v1       = (const float*)d_in[11];
    const float* W_v2       = (const float*)d_in[12];
    const float* b_v2       = (const float*)d_in[13];
    const float* W_p        = (const float*)d_in[14];
    const float* b_p        = (const float*)d_in[15];
    const float* gam        = (const float*)d_in[16];
    const float* bet        = (const float*)d_in[17];
    const float* bn_m       = (const float*)d_in[18];
    const float* bn_v       = (const float*)d_in[19];

    float* dout     = (float*)d_out;
    float* out_attn = dout + BB * VF;
    float* out_ctx  = out_attn + BB * SS;

    kA_all<<<1664, 256>>>(hh, cc, dec_output, W_dec, b_dec,
                          (const float4*)enc1, (const float4*)w_attn,
                          (const float4*)enc, src, out_attn,
                          bn_m, bn_v, gam, bet, W_p, b_p, dinp, out_ctx);
    kC_hidden_logits<<<432, 256>>>(W_v1, b_v1, W_v2);
    kD_exp_final  <<<dim3(32, NCB), 256>>>(b_v2, dout, src);
}

// round 15
// speedup vs baseline: 1.0688x; 1.0368x over previous
#include <cuda_runtime.h>

#define BB   32
#define SS   1024
#define DD   512
#define D2   1024
#define D3   1536
#define VV   49000
#define VP   49152
#define VF   50000
#define NCB  25
#define KB6  12
#define JB6  4

__device__ __align__(16) float g_temp_t [D3 * BB];
__device__ __align__(16) float g_dpart  [4 * BB * D2];
__device__ __align__(16) float g_dec1   [BB * D2];
__device__ __align__(16) float g_scores [BB * SS];
__device__ __align__(16) float g_attn   [BB * SS];
__device__ __align__(16) float g_cp2    [1024 * D2];
__device__            float g_mb     [1024];
__device__            float g_sb     [1024];
__device__ __align__(16) float g_hpart  [KB6 * BB * DD];
__device__ __align__(16) float g_hidden [BB * DD];
__device__            float g_pgen  [BB];
__device__            float g_pgen_acc[BB];
__device__ __align__(16) float g_lpart [2 * BB * VP];
__device__            float g_sumtot[BB];
__device__            int   g_ctr_d  [128];
__device__            int   g_ctr_dec1;
__device__            int   g_ctr_c2 [BB];
__device__            int   g_ctr_cb [BB];
__device__            int   g_ctr_v  [BB];
__device__            int   g_ctr_h  [JB6];
__device__            int   g_hready;

__device__ __forceinline__ float fast_tanh(float x) {
    float y;
    asm("tanh.approx.f32 %0, %1;" : "=f"(y) : "f"(x));
    return y;
}

// ===========================================================================
// A: dec1 split-K (bids 0..511) + score/pctx (512..1535) + combiners (1536..1663)
// ===========================================================================
__global__ void __launch_bounds__(256, 5)
kA_all(const float* __restrict__ h, const float* __restrict__ c,
       const float* __restrict__ dec_output,
       const float* __restrict__ W, const float* __restrict__ bias,
       const float4* __restrict__ enc1, const float4* __restrict__ wattn,
       const float4* __restrict__ enc, const int* __restrict__ src,
       float* __restrict__ out_attn,
       const float* __restrict__ bn_m, const float* __restrict__ bn_v,
       const float* __restrict__ gam,  const float* __restrict__ bet,
       const float* __restrict__ Wp,   const float* __restrict__ bp,
       const float* __restrict__ dinp, float* __restrict__ out_ctx) {
    __shared__ __align__(16) float abuf[5152];
    __shared__ float sscore[32];
    __shared__ float sp[32];
    __shared__ float sred[8];
    __shared__ int slast;
    int t = threadIdx.x;
    int bid = blockIdx.x;

    if (bid < 512) {
        // ---- dec1 split-K: jb = bid>>2 (8 j), ks = bid&3 (256 k) ----
        int jb = bid >> 2, ks = bid & 3;
        int j0 = jb * 8;
        float* sdec = abuf;            // [32][129]
        float* sW   = abuf + 4128;     // [8][128]
        int jj = t >> 5, b = t & 31;
        if (bid < 128 && t < 128) {
            int i = bid * 128 + t;
            int k = i >> 5, bb = i & 31;
            g_temp_t[i] = dec_output[bb * DD + k];
        }
        float a0 = 0.f, a1 = 0.f, a2 = 0.f, a3 = 0.f;
#pragma unroll
        for (int ch = 0; ch < 2; ch++) {
            int k0 = ks * 256 + ch * 128;
            __syncthreads();
#pragma unroll
            for (int m = 0; m < 16; m++) {
                int e = m * 256 + t;
                int bb = e >> 7, kk = e & 127;
                int kg = k0 + kk;
                sdec[bb * 129 + kk] = (kg < DD) ? h[bb * DD + kg] : c[bb * DD + kg - DD];
            }
#pragma unroll
            for (int m = 0; m < 4; m++) {
                int e = m * 256 + t;
                int jx = e >> 7, kk = e & 127;
                sW[jx * 128 + kk] = W[(j0 + jx) * D2 + k0 + kk];
            }
            __syncthreads();
#pragma unroll
            for (int kk = 0; kk < 128; kk += 4) {
                a0 += sW[jj * 128 + kk + 0] * sdec[b * 129 + kk + 0];
                a1 += sW[jj * 128 + kk + 1] * sdec[b * 129 + kk + 1];
                a2 += sW[jj * 128 + kk + 2] * sdec[b * 129 + kk + 2];
                a3 += sW[jj * 128 + kk + 3] * sdec[b * 129 + kk + 3];
            }
        }
        g_dpart[(ks * 32 + b) * D2 + j0 + jj] = (a0 + a1) + (a2 + a3);
        __syncthreads();
        if (t == 0) {
            __threadfence();
            int old = atomicAdd(&g_ctr_d[jb], 1);
            slast = (old == 3);
        }
        __syncthreads();
        if (!slast) return;
        __threadfence();
        float tot = bias[j0 + jj];
#pragma unroll
        for (int ks2 = 0; ks2 < 4; ks2++)
            tot += __ldcg(&g_dpart[(ks2 * 32 + b) * D2 + j0 + jj]);
        g_dec1[b * D2 + j0 + jj] = tot;
        __threadfence();
        __syncthreads();
        if (t == 0) atomicAdd(&g_ctr_dec1, 1);
        return;
    }

    if (bid < 1536) {
        // ---- score (row-interleaved MLP) + local softmax + partial context ----
        float4* sd1 = (float4*)abuf;          // [256]
        float4* swa = ((float4*)abuf) + 256;  // [256]
        int idx = bid - 512;                  // 0..1023
        int b = idx >> 5, sb32 = idx & 31;
        int row0 = b * SS + sb32 * 32;
        swa[t] = wattn[t];
        if (t == 0) {
            while (*(volatile int*)&g_ctr_dec1 < 128) __nanosleep(64);
        }
        __syncthreads();
        __threadfence();
        sd1[t] = __ldcg(((const float4*)g_dec1) + b * 256 + t);
        __syncthreads();
        int lane = t & 31, w = t >> 5;
        const float4* er = enc1 + (size_t)(row0 + w * 4) * 256 + lane;
        float ac0 = 0.f, ac1 = 0.f, ac2 = 0.f, ac3 = 0.f;
#pragma unroll
        for (int i = 0; i < 8; i++) {
            int cidx = i * 32 + lane;
            float4 e0 = er[i * 32];
            float4 e1 = er[256 + i * 32];
            float4 e2 = er[512 + i * 32];
            float4 e3 = er[768 + i * 32];
            float4 dd = sd1[cidx];
            float4 wa = swa[cidx];
            ac0 += fast_tanh(e0.x + dd.x) * wa.x + fast_tanh(e0.y + dd.y) * wa.y
                 + fast_tanh(e0.z + dd.z) * wa.z + fast_tanh(e0.w + dd.w) * wa.w;
            ac1 += fast_tanh(e1.x + dd.x) * wa.x + fast_tanh(e1.y + dd.y) * wa.y
                 + fast_tanh(e1.z + dd.z) * wa.z + fast_tanh(e1.w + dd.w) * wa.w;
            ac2 += fast_tanh(e2.x + dd.x) * wa.x + fast_tanh(e2.y + dd.y) * wa.y
                 + fast_tanh(e2.z + dd.z) * wa.z + fast_tanh(e2.w + dd.w) * wa.w;
            ac3 += fast_tanh(e3.x + dd.x) * wa.x + fast_tanh(e3.y + dd.y) * wa.y
                 + fast_tanh(e3.z + dd.z) * wa.z + fast_tanh(e3.w + dd.w) * wa.w;
        }
#pragma unroll
        for (int o = 16; o; o >>= 1) {
            ac0 += __shfl_down_sync(0xffffffffu, ac0, o);
            ac1 += __shfl_down_sync(0xffffffffu, ac1, o);
            ac2 += __shfl_down_sync(0xffffffffu, ac2, o);
            ac3 += __shfl_down_sync(0xffffffffu, ac3, o);
        }
        if (!lane) {
            int lr = w * 4;
            sscore[lr + 0] = ac0; g_scores[row0 + lr + 0] = ac0;
            sscore[lr + 1] = ac1; g_scores[row0 + lr + 1] = ac1;
            sscore[lr + 2] = ac2; g_scores[row0 + lr + 2] = ac2;
            sscore[lr + 3] = ac3; g_scores[row0 + lr + 3] = ac3;
        }
        __syncthreads();
        float m = sscore[0];
#pragma unroll
        for (int i = 1; i < 32; i++) m = fmaxf(m, sscore[i]);
        if (t < 32) {
            int sv = src[row0 + t];
            sp[t] = (sv != 0) ? __expf(sscore[t] - m) : 0.f;
        }
        __syncthreads();
        if (t == 0) {
            float sum = 0.f;
#pragma unroll
            for (int i = 0; i < 32; i++) sum += sp[i];
            g_mb[idx] = m;
            g_sb[idx] = sum;
        }
        float4 acc4 = make_float4(0.f, 0.f, 0.f, 0.f);
        const float4* ebase = enc + (size_t)row0 * 256 + t;
#pragma unroll 8
        for (int i = 0; i < 32; i++) {
            float pi = sp[i];
            float4 ee = ebase[(size_t)i * 256];
            acc4.x += pi * ee.x; acc4.y += pi * ee.y;
            acc4.z += pi * ee.z; acc4.w += pi * ee.w;
        }
        ((float4*)g_cp2)[idx * 256 + t] = acc4;
        __threadfence();
        __syncthreads();
        if (t == 0) atomicAdd(&g_ctr_c2[b], 1);
        return;
    }

    // ---- combiners: 4 per b, 256 dims each ----
    {
        int idx = bid - 1536;       // 0..127
        int b = idx >> 2, ch = idx & 3;
        float* sw2 = abuf;          // [32]
        float* smv = abuf + 32;     // [32]
        float* ssv = abuf + 64;     // [32]
        if (t == 0) {
            while (*(volatile int*)&g_ctr_c2[b] < 32) __nanosleep(64);
        }
        __syncthreads();
        __threadfence();
        if (t < 32) {
            smv[t] = __ldcg(&g_mb[b * 32 + t]);
            ssv[t] = __ldcg(&g_sb[b * 32 + t]);
        }
        __syncthreads();
        float M = smv[0];
#pragma unroll
        for (int i = 1; i < 32; i++) M = fmaxf(M, smv[i]);
        if (t < 32) sw2[t] = __expf(smv[t] - M);
        __syncthreads();
        float Z = 0.f;
#pragma unroll
        for (int i = 0; i < 32; i++) Z += sw2[i] * ssv[i];
        float invZ = 1.f / Z;
        int d = ch * 256 + t;
        float acA = 0.f, acB = 0.f;
#pragma unroll 8
        for (int i = 0; i < 32; i += 2) {
            acA += sw2[i]     * __ldcg(&g_cp2[(size_t)(b * 32 + i)     * D2 + d]);
            acB += sw2[i + 1] * __ldcg(&g_cp2[(size_t)(b * 32 + i + 1) * D2 + d]);
        }
        float ctxv = (acA + acB) * invZ;
        float cx = (ctxv - bn_m[d]) * rsqrtf(bn_v[d] + 1e-5f) * gam[d] + bet[d];
        out_ctx[b * D2 + d] = cx;
        g_temp_t[(DD + d) * 32 + b] = cx;
        float pg = Wp[d] * cx;
        if (ch == 0) {
#pragma unroll
            for (int dd = 0; dd < 4; dd++) {
                int d2 = dd * 256 + t;
                float dop = (d2 < DD) ? h[b * DD + d2] : c[b * DD + d2 - DD];
                pg += Wp[D2 + d2] * dop;
            }
#pragma unroll
            for (int dd = 0; dd < 2; dd++) {
                int d2 = dd * 256 + t;
                pg += Wp[2048 + d2] * dinp[b * DD + d2];
            }
            float4 sc4 = ((const float4*)g_scores)[b * 256 + t];
            int4   id4 = ((const int4*)src)[b * 256 + t];
            float4 a4;
            a4.x = (id4.x != 0) ? __expf(sc4.x - M) * invZ : 0.f;
            a4.y = (id4.y != 0) ? __expf(sc4.y - M) * invZ : 0.f;
            a4.z = (id4.z != 0) ? __expf(sc4.z - M) * invZ : 0.f;
            a4.w = (id4.w != 0) ? __expf(sc4.w - M) * invZ : 0.f;
            ((float4*)g_attn)[b * 256 + t] = a4;
            ((float4*)out_attn)[b * 256 + t] = a4;
        }
#pragma unroll
        for (int o = 16; o; o >>= 1) pg += __shfl_down_sync(0xffffffffu, pg, o);
        if (!(t & 31)) sred[t >> 5] = pg;
        __syncthreads();
        if (t == 0) {
            float tot = 0.f;
#pragma unroll
            for (int i = 0; i < 8; i++) tot += sred[i];
            atomicAdd(&g_pgen_acc[b], tot);
            __threadfence();
            int old = atomicAdd(&g_ctr_cb[b], 1);
            slast = (old == 3);
        }
        __syncthreads();
        if (slast && t == 0) {
            __threadfence();
            float tot = __ldcg(&g_pgen_acc[b]) + bp[0];
            g_pgen[b] = 1.f / (1.f + __expf(-tot));
        }
    }
}

// ===========================================================================
// C: fused k6 (hidden GEMM, bids 0..47) + k8a (vocab logits, bids 48..431)
// ===========================================================================
#define XS6  68
#define WSTR 20
__global__ void __launch_bounds__(256, 2)
kC_hidden_logits(const float* __restrict__ Wv1, const float* __restrict__ bv1,
                 const float* __restrict__ Wv2) {
    __shared__ __align__(16) float cbuf[10880];
    __shared__ int slast;
    int t = threadIdx.x;
    int bid = blockIdx.x;

    if (bid < 48) {
        float* sW = cbuf;
        float* sX = cbuf + 128 * XS6;
        int tj = t & 63, tb = t >> 6;
        int jb = bid & 3, kb = bid >> 2;
        int j0 = jb * 128;
        unsigned long long acc2[2][8];
#pragma unroll
        for (int jr = 0; jr < 2; jr++)
#pragma unroll
            for (int bj = 0; bj < 8; bj++) acc2[jr][bj] = 0ull;
#pragma unroll
        for (int sub = 0; sub < 2; sub++) {
            int k0s = kb * 128 + sub * 64;
            __syncthreads();
#pragma unroll
            for (int li = 0; li < 8; li++) {
                int flat = li * 256 + t;
                int row = flat >> 4, kc = flat & 15;
                float4 f = *(const float4*)(Wv1 + (size_t)(j0 + row) * D3 + k0s + kc * 4);
                *(float4*)(sW + row * XS6 + kc * 4) = f;
            }
#pragma unroll
            for (int li = 0; li < 2; li++) {
                int flat = li * 256 + t;
                int kk = flat >> 3, bq = flat & 7;
                float4 f = ((const float4*)g_temp_t)[(size_t)(k0s + kk) * 8 + bq];
                sX[(bq * 4 + 0) * XS6 + kk] = f.x;
                sX[(bq * 4 + 1) * XS6 + kk] = f.y;
                sX[(bq * 4 + 2) * XS6 + kk] = f.z;
                sX[(bq * 4 + 3) * XS6 + kk] = f.w;
            }
            __syncthreads();
#pragma unroll
            for (int kq = 0; kq < 16; kq++) {
                ulonglong2 xv[8];
#pragma unroll
                for (int bj = 0; bj < 8; bj++)
                    xv[bj] = *(const ulonglong2*)(sX + (tb * 8 + bj) * XS6 + kq * 4);
#pragma unroll
                for (int jr = 0; jr < 2; jr++) {
                    ulonglong2 wv = *(const ulonglong2*)(sW + (jr * 64 + tj) * XS6 + kq * 4);
#pragma unroll
                    for (int bj = 0; bj < 8; bj++) {
                        asm("fma.rn.f32x2 %0, %1, %2, %0;"
                            : "+l"(acc2[jr][bj]) : "l"(wv.x), "l"(xv[bj].x));
                        asm("fma.rn.f32x2 %0, %1, %2, %0;"
                            : "+l"(acc2[jr][bj]) : "l"(wv.y), "l"(xv[bj].y));
                    }
                }
            }
        }
#pragma unroll
        for (int jr = 0; jr < 2; jr++)
#pragma unroll
            for (int bj = 0; bj < 8; bj++) {
                unsigned long long a = acc2[jr][bj];
                float v = __uint_as_float((unsigned)(a & 0xffffffffu)) +
                          __uint_as_float((unsigned)(a >> 32));
                g_hpart[((size_t)kb * 32 + tb * 8 + bj) * DD + j0 + jr * 64 + tj] = v;
            }
        __syncthreads();
        if (t == 0) {
            __threadfence();
            int old = atomicAdd(&g_ctr_h[jb], 1);
            slast = (old == KB6 - 1);
        }
        __syncthreads();
        if (!slast) return;
        __threadfence();
#pragma unroll
        for (int li = 0; li < 4; li++) {
            int flat = li * 256 + t;
            int b = flat >> 5, jq = flat & 31;
            float4 sum = *(const float4*)(bv1 + j0 + jq * 4);
#pragma unroll
            for (int p = 0; p < KB6; p++) {
                float4 v = __ldcg((const float4*)(g_hpart + ((size_t)p * 32 + b) * DD + j0 + jq * 4));
                sum.x += v.x; sum.y += v.y; sum.z += v.z; sum.w += v.w;
            }
            *(float4*)(g_hidden + (size_t)b * DD + j0 + jq * 4) = sum;
        }
        __threadfence();
        __syncthreads();
        if (t == 0) atomicAdd(&g_hready, 1);
        return;
    }

    // ---- k8a part ----
    float* Ws = cbuf;
    float* Hs = cbuf + 256 * WSTR;
    int idx = bid - 48;
    if (idx == 0 && t < BB) { g_sumtot[t] = 0.f; g_ctr_v[t] = 0; }
    int tv = t & 63, tb = t >> 6;
    int v0 = (idx % 192) * 256;
    int ks = idx / 192;
    int kbase = ks * 256;

    unsigned long long acc2[4][8];
#pragma unroll
    for (int j = 0; j < 4; j++)
#pragma unroll
        for (int bj = 0; bj < 8; bj++) acc2[j][bj] = 0ull;

    float4 wreg[4];
    float  hreg0, hreg1;
    {
        int k0 = kbase;
#pragma unroll
        for (int li = 0; li < 4; li++) {
            int flat = li * 256 + t;
            int v = flat >> 2, kq = flat & 3;
            int gv = v0 + v;
            wreg[li] = (gv < VV)
                ? *(const float4*)(Wv2 + (size_t)gv * DD + k0 + kq * 4)
                : make_float4(0.f, 0.f, 0.f, 0.f);
        }
#pragma unroll
        for (int li = 0; li < 4; li++) {
            int flat = li * 256 + t;
            int v = flat >> 2, kq = flat & 3;
            *(float4*)(Ws + v * WSTR + kq * 4) = wreg[li];
        }
    }
    if (t == 0) {
        while (*(volatile int*)&g_hready < JB6) __nanosleep(64);
    }
    __syncthreads();
    __threadfence();
    {
        int k0 = kbase;
        hreg0 = __ldcg(&g_hidden[((t)       >> 4) * DD + k0 + ((t)       & 15)]);
        hreg1 = __ldcg(&g_hidden[((t + 256) >> 4) * DD + k0 + ((t + 256) & 15)]);
        Hs[t] = hreg0;
        Hs[t + 256] = hreg1;
    }
    __syncthreads();

    for (int tile = 0; tile < 16; tile++) {
        if (tile < 15) {
            int k0 = kbase + (tile + 1) * 16;
#pragma unroll
            for (int li = 0; li < 4; li++) {
                int flat = li * 256 + t;
                int v = flat >> 2, kq = flat & 3;
                int gv = v0 + v;
                wreg[li] = (gv < VV)
                    ? *(const float4*)(Wv2 + (size_t)gv * DD + k0 + kq * 4)
                    : make_float4(0.f, 0.f, 0.f, 0.f);
            }
            hreg0 = g_hidden[((t)       >> 4) * DD + k0 + ((t)       & 15)];
            hreg1 = g_hidden[((t + 256) >> 4) * DD + k0 + ((t + 256) & 15)];
        }
#pragma unroll
        for (int kq = 0; kq < 4; kq++) {
            ulonglong2 h2[8];
#pragma unroll
            for (int bj = 0; bj < 8; bj++)
                h2[bj] = *(const ulonglong2*)(Hs + (tb * 8 + bj) * 16 + kq * 4);
#pragma unroll
            for (int j = 0; j < 4; j++) {
                ulonglong2 w2 = *(const ulonglong2*)(Ws + (tv + 64 * j) * WSTR + kq * 4);
#pragma unroll
                for (int bj = 0; bj < 8; bj++) {
                    asm("fma.rn.f32x2 %0, %1, %2, %0;"
                        : "+l"(acc2[j][bj]) : "l"(w2.x), "l"(h2[bj].x));
                    asm("fma.rn.f32x2 %0, %1, %2, %0;"
                        : "+l"(acc2[j][bj]) : "l"(w2.y), "l"(h2[bj].y));
                }
            }
        }
        if (tile < 15) {
            __syncthreads();
#pragma unroll
            for (int li = 0; li < 4; li++) {
                int flat = li * 256 + t;
                int v = flat >> 2, kq = flat & 3;
                *(float4*)(Ws + v * WSTR + kq * 4) = wreg[li];
            }
            Hs[t] = hreg0;
            Hs[t + 256] = hreg1;
            __syncthreads();
        }
    }
    float accf[4][8];
#pragma unroll
    for (int j = 0; j < 4; j++)
#pragma unroll
        for (int bj = 0; bj < 8; bj++) {
            unsigned long long a = acc2[j][bj];
            accf[j][bj] = __uint_as_float((unsigned)(a & 0xffffffffu)) +
                          __uint_as_float((unsigned)(a >> 32));
        }
#pragma unroll
    for (int p = 0; p < 2; p++) {
        __syncthreads();
        if ((tb >> 1) == p) {
#pragma unroll
            for (int j = 0; j < 4; j++)
#pragma unroll
                for (int bj = 0; bj < 8; bj++)
                    Ws[((tb & 1) * 8 + bj) * 256 + tv + 64 * j] = accf[j][bj];
        }
        __syncthreads();
#pragma unroll
        for (int i = 0; i < 4; i++) {
            int ii = i * 256 + t;
            int row = ii >> 6, col = ii & 63;
            *(float4*)(g_lpart + ((size_t)(ks * 32 + p * 16 + row) * VP + v0 + col * 4)) =
                *(const float4*)(Ws + row * 256 + col * 4);
        }
    }
}

// ===========================================================================
// D: exp (regs) + per-b sum; local smem scatter; spin on sum counter only;
//    single-pass combine + zero-fix. Zeroes kA counters for next replay.
// ===========================================================================
__global__ void kD_exp_final(const float* __restrict__ bv2, float* __restrict__ dout,
                             const int* __restrict__ src) {
    __shared__ float ssc[2048];
    __shared__ float sm[8];
    int b = blockIdx.x, cb = blockIdx.y, t = threadIdx.x;
    if (b == 0 && cb == 0) {
        if (t == 0) { g_ctr_dec1 = 0; g_hready = 0; }
        if (t < BB) { g_ctr_c2[t] = 0; g_ctr_cb[t] = 0; g_pgen_acc[t] = 0.f; }
        if (t < 128) g_ctr_d[t] = 0;
        if (t < JB6) g_ctr_h[t] = 0;
    }
    int base = cb * 2048;
    float pg = g_pgen[b];
    float ev[8];
    float sum = 0.f;
#pragma unroll
    for (int it = 0; it < 8; it++) {
        int v = base + it * 256 + t;
        float e = 0.f;
        if (v < VV) {
            float l = g_lpart[(size_t)b * VP + v] + g_lpart[(size_t)(32 + b) * VP + v] + bv2[v];
            e = __expf(l);
            sum += e;
        }
        ev[it] = e;
    }
#pragma unroll
    for (int o = 16; o; o >>= 1) sum += __shfl_down_sync(0xffffffffu, sum, o);
    if (!(t & 31)) sm[t >> 5] = sum;
    __syncthreads();
    if (t == 0) {
        float tot = 0.f;
#pragma unroll
        for (int i = 0; i < 8; i++) tot += sm[i];
        atomicAdd(&g_sumtot[b], tot);
        __threadfence();
        atomicAdd(&g_ctr_v[b], 1);
    }
#pragma unroll
    for (int i = 0; i < 8; i++) ssc[i * 256 + t] = 0.f;
    __syncthreads();
#pragma unroll
    for (int i = 0; i < 4; i++) {
        int si = i * 256 + t;
        int idx = src[b * SS + si];
        int off = idx - base;
        if ((unsigned)off < 2048u)
            atomicAdd(&ssc[off], g_attn[b * SS + si]);
    }
    __syncthreads();
    if (t == 0) {
        while (*(volatile int*)&g_ctr_v[b] < NCB) __nanosleep(32);
    }
    __syncthreads();
    __threadfence();
    float s  = __ldcg(&g_sumtot[b]);
    float sc = pg / s;
    float f  = 1.f - pg;
#pragma unroll
    for (int it = 0; it < 8; it++) {
        int v = base + it * 256 + t;
        if (v < VF) {
            float p = ev[it] * sc + f * ssc[it * 256 + t];
            if (p == 0.f) p = 1e-12f;
            dout[(size_t)b * VF + v] = p;
        }
    }
}

extern "C" void kernel_launch(void* const* d_in, const int* in_sizes, int n_in,
                              void* d_out, int out_size) {
    const float* dec_output = (const float*)d_in[0];
    const float* hh         = (const float*)d_in[1];
    const float* cc         = (const float*)d_in[2];
    const float* dinp       = (const float*)d_in[3];
    const float* enc        = (const float*)d_in[4];
    const float* enc1       = (const float*)d_in[5];
    const int*   src        = (const int*)  d_in[6];
    const float* W_dec      = (const float*)d_in[7];
    const float* b_dec      = (const float*)d_in[8];
    const float* w_attn     = (const float*)d_in[9];
    const float* W_v1       = (const float*)d_in[10];
    const float* b_v1       = (const float*)d_in[11];
    const float* W_v2       = (const float*)d_in[12];
    const float* b_v2       = (const float*)d_in[13];
    const float* W_p        = (const float*)d_in[14];
    const float* b_p        = (const float*)d_in[15];
    const float* gam        = (const float*)d_in[16];
    const float* bet        = (const float*)d_in[17];
    const float* bn_m       = (const float*)d_in[18];
    const float* bn_v       = (const float*)d_in[19];

    float* dout     = (float*)d_out;
    float* out_attn = dout + BB * VF;
    float* out_ctx  = out_attn + BB * SS;

    kA_all<<<1664, 256>>>(hh, cc, dec_output, W_dec, b_dec,
                          (const float4*)enc1, (const float4*)w_attn,
                          (const float4*)enc, src, out_attn,
                          bn_m, bn_v, gam, bet, W_p, b_p, dinp, out_ctx);
    kC_hidden_logits<<<432, 256>>>(W_v1, b_v1, W_v2);
    kD_exp_final  <<<dim3(32, NCB), 256>>>(b_v2, dout, src);
}

// round 16
// speedup vs baseline: 1.1053x; 1.0341x over previous
#include <cuda_runtime.h>

#define BB   32
#define SS   1024
#define DD   512
#define D2   1024
#define D3   1536
#define VV   49000
#define VP   49152
#define VF   50000
#define NCB  25
#define KB6  24
#define JB6  4

__device__ __align__(16) float g_temp_t [D3 * BB];
__device__ __align__(16) float g_dpart  [4 * BB * D2];
__device__ __align__(16) float g_dec1   [BB * D2];
__device__ __align__(16) float g_scores [BB * SS];
__device__ __align__(16) float g_attn   [BB * SS];
__device__ __align__(16) float g_cp2    [1024 * D2];
__device__            float g_mb     [1024];
__device__            float g_sb     [1024];
__device__ __align__(16) float g_hpart  [KB6 * BB * DD];
__device__ __align__(16) float g_hidden [BB * DD];
__device__            float g_pgen  [BB];
__device__            float g_pgen_acc[BB];
__device__ __align__(16) float g_lpart [2 * BB * VP];
__device__            float g_sumtot[BB];
__device__            int   g_ctr_d  [128];
__device__            int   g_ctr_dec1;
__device__            int   g_ctr_c2 [BB];
__device__            int   g_ctr_cb [BB];
__device__            int   g_ctr_v  [BB];
__device__            int   g_ctr_h  [JB6];
__device__            int   g_hready;

__device__ __forceinline__ float fast_tanh(float x) {
    float y;
    asm("tanh.approx.f32 %0, %1;" : "=f"(y) : "f"(x));
    return y;
}

// ===========================================================================
// A: dec1 split-K (bids 0..511) + score/pctx (512..1535) + combiners (1536..1663)
// ===========================================================================
__global__ void __launch_bounds__(256, 5)
kA_all(const float* __restrict__ h, const float* __restrict__ c,
       const float* __restrict__ dec_output,
       const float* __restrict__ W, const float* __restrict__ bias,
       const float4* __restrict__ enc1, const float4* __restrict__ wattn,
       const float4* __restrict__ enc, const int* __restrict__ src,
       float* __restrict__ out_attn,
       const float* __restrict__ bn_m, const float* __restrict__ bn_v,
       const float* __restrict__ gam,  const float* __restrict__ bet,
       const float* __restrict__ Wp,   const float* __restrict__ bp,
       const float* __restrict__ dinp, float* __restrict__ out_ctx) {
    __shared__ __align__(16) float abuf[5152];
    __shared__ float sscore[32];
    __shared__ float sp[32];
    __shared__ float sred[8];
    __shared__ int slast;
    int t = threadIdx.x;
    int bid = blockIdx.x;

    if (bid < 512) {
        // ---- dec1 split-K: jb = bid>>2 (8 j), ks = bid&3 (256 k) ----
        int jb = bid >> 2, ks = bid & 3;
        int j0 = jb * 8;
        float* sdec = abuf;            // [32][129]
        float* sW   = abuf + 4128;     // [8][128]
        int jj = t >> 5, b = t & 31;
        if (bid < 128 && t < 128) {
            int i = bid * 128 + t;
            int k = i >> 5, bb = i & 31;
            g_temp_t[i] = dec_output[bb * DD + k];
        }
        float a0 = 0.f, a1 = 0.f, a2 = 0.f, a3 = 0.f;
#pragma unroll
        for (int ch = 0; ch < 2; ch++) {
            int k0 = ks * 256 + ch * 128;
            __syncthreads();
#pragma unroll
            for (int m = 0; m < 16; m++) {
                int e = m * 256 + t;
                int bb = e >> 7, kk = e & 127;
                int kg = k0 + kk;
                sdec[bb * 129 + kk] = (kg < DD) ? h[bb * DD + kg] : c[bb * DD + kg - DD];
            }
#pragma unroll
            for (int m = 0; m < 4; m++) {
                int e = m * 256 + t;
                int jx = e >> 7, kk = e & 127;
                sW[jx * 128 + kk] = W[(j0 + jx) * D2 + k0 + kk];
            }
            __syncthreads();
#pragma unroll
            for (int kk = 0; kk < 128; kk += 4) {
                a0 += sW[jj * 128 + kk + 0] * sdec[b * 129 + kk + 0];
                a1 += sW[jj * 128 + kk + 1] * sdec[b * 129 + kk + 1];
                a2 += sW[jj * 128 + kk + 2] * sdec[b * 129 + kk + 2];
                a3 += sW[jj * 128 + kk + 3] * sdec[b * 129 + kk + 3];
            }
        }
        g_dpart[(ks * 32 + b) * D2 + j0 + jj] = (a0 + a1) + (a2 + a3);
        __syncthreads();
        if (t == 0) {
            __threadfence();
            int old = atomicAdd(&g_ctr_d[jb], 1);
            slast = (old == 3);
        }
        __syncthreads();
        if (!slast) return;
        __threadfence();
        float tot = bias[j0 + jj];
#pragma unroll
        for (int ks2 = 0; ks2 < 4; ks2++)
            tot += __ldcg(&g_dpart[(ks2 * 32 + b) * D2 + j0 + jj]);
        g_dec1[b * D2 + j0 + jj] = tot;
        __threadfence();
        __syncthreads();
        if (t == 0) atomicAdd(&g_ctr_dec1, 1);
        return;
    }

    if (bid < 1536) {
        // ---- score (row-interleaved MLP) + local softmax + partial context ----
        float4* sd1 = (float4*)abuf;          // [256]
        float4* swa = ((float4*)abuf) + 256;  // [256]
        int idx = bid - 512;                  // 0..1023
        int b = idx >> 5, sb32 = idx & 31;
        int row0 = b * SS + sb32 * 32;
        swa[t] = wattn[t];
        if (t == 0) {
            while (*(volatile int*)&g_ctr_dec1 < 128) __nanosleep(64);
        }
        __syncthreads();
        __threadfence();
        sd1[t] = __ldcg(((const float4*)g_dec1) + b * 256 + t);
        __syncthreads();
        int lane = t & 31, w = t >> 5;
        const float4* er = enc1 + (size_t)(row0 + w * 4) * 256 + lane;
        float ac0 = 0.f, ac1 = 0.f, ac2 = 0.f, ac3 = 0.f;
#pragma unroll
        for (int i = 0; i < 8; i++) {
            int cidx = i * 32 + lane;
            float4 e0 = __ldcs(er + i * 32);
            float4 e1 = __ldcs(er + 256 + i * 32);
            float4 e2 = __ldcs(er + 512 + i * 32);
            float4 e3 = __ldcs(er + 768 + i * 32);
            float4 dd = sd1[cidx];
            float4 wa = swa[cidx];
            ac0 += fast_tanh(e0.x + dd.x) * wa.x + fast_tanh(e0.y + dd.y) * wa.y
                 + fast_tanh(e0.z + dd.z) * wa.z + fast_tanh(e0.w + dd.w) * wa.w;
            ac1 += fast_tanh(e1.x + dd.x) * wa.x + fast_tanh(e1.y + dd.y) * wa.y
                 + fast_tanh(e1.z + dd.z) * wa.z + fast_tanh(e1.w + dd.w) * wa.w;
            ac2 += fast_tanh(e2.x + dd.x) * wa.x + fast_tanh(e2.y + dd.y) * wa.y
                 + fast_tanh(e2.z + dd.z) * wa.z + fast_tanh(e2.w + dd.w) * wa.w;
            ac3 += fast_tanh(e3.x + dd.x) * wa.x + fast_tanh(e3.y + dd.y) * wa.y
                 + fast_tanh(e3.z + dd.z) * wa.z + fast_tanh(e3.w + dd.w) * wa.w;
        }
#pragma unroll
        for (int o = 16; o; o >>= 1) {
            ac0 += __shfl_down_sync(0xffffffffu, ac0, o);
            ac1 += __shfl_down_sync(0xffffffffu, ac1, o);
            ac2 += __shfl_down_sync(0xffffffffu, ac2, o);
            ac3 += __shfl_down_sync(0xffffffffu, ac3, o);
        }
        if (!lane) {
            int lr = w * 4;
            sscore[lr + 0] = ac0; g_scores[row0 + lr + 0] = ac0;
            sscore[lr + 1] = ac1; g_scores[row0 + lr + 1] = ac1;
            sscore[lr + 2] = ac2; g_scores[row0 + lr + 2] = ac2;
            sscore[lr + 3] = ac3; g_scores[row0 + lr + 3] = ac3;
        }
        __syncthreads();
        float m = sscore[0];
#pragma unroll
        for (int i = 1; i < 32; i++) m = fmaxf(m, sscore[i]);
        if (t < 32) {
            int sv = src[row0 + t];
            sp[t] = (sv != 0) ? __expf(sscore[t] - m) : 0.f;
        }
        __syncthreads();
        if (t == 0) {
            float sum = 0.f;
#pragma unroll
            for (int i = 0; i < 32; i++) sum += sp[i];
            g_mb[idx] = m;
            g_sb[idx] = sum;
        }
        float4 acc4 = make_float4(0.f, 0.f, 0.f, 0.f);
        const float4* ebase = enc + (size_t)row0 * 256 + t;
#pragma unroll 8
        for (int i = 0; i < 32; i++) {
            float pi = sp[i];
            float4 ee = __ldcs(ebase + (size_t)i * 256);
            acc4.x += pi * ee.x; acc4.y += pi * ee.y;
            acc4.z += pi * ee.z; acc4.w += pi * ee.w;
        }
        ((float4*)g_cp2)[idx * 256 + t] = acc4;
        __threadfence();
        __syncthreads();
        if (t == 0) atomicAdd(&g_ctr_c2[b], 1);
        return;
    }

    // ---- combiners: 4 per b, 256 dims each ----
    {
        int idx = bid - 1536;       // 0..127
        int b = idx >> 2, ch = idx & 3;
        float* sw2 = abuf;          // [32]
        float* smv = abuf + 32;     // [32]
        float* ssv = abuf + 64;     // [32]
        if (t == 0) {
            while (*(volatile int*)&g_ctr_c2[b] < 32) __nanosleep(64);
        }
        __syncthreads();
        __threadfence();
        if (t < 32) {
            smv[t] = __ldcg(&g_mb[b * 32 + t]);
            ssv[t] = __ldcg(&g_sb[b * 32 + t]);
        }
        __syncthreads();
        float M = smv[0];
#pragma unroll
        for (int i = 1; i < 32; i++) M = fmaxf(M, smv[i]);
        if (t < 32) sw2[t] = __expf(smv[t] - M);
        __syncthreads();
        float Z = 0.f;
#pragma unroll
        for (int i = 0; i < 32; i++) Z += sw2[i] * ssv[i];
        float invZ = 1.f / Z;
        int d = ch * 256 + t;
        float acA = 0.f, acB = 0.f;
#pragma unroll 8
        for (int i = 0; i < 32; i += 2) {
            acA += sw2[i]     * __ldcg(&g_cp2[(size_t)(b * 32 + i)     * D2 + d]);
            acB += sw2[i + 1] * __ldcg(&g_cp2[(size_t)(b * 32 + i + 1) * D2 + d]);
        }
        float ctxv = (acA + acB) * invZ;
        float cx = (ctxv - bn_m[d]) * rsqrtf(bn_v[d] + 1e-5f) * gam[d] + bet[d];
        out_ctx[b * D2 + d] = cx;
        g_temp_t[(DD + d) * 32 + b] = cx;
        float pg = Wp[d] * cx;
        if (ch == 0) {
#pragma unroll
            for (int dd = 0; dd < 4; dd++) {
                int d2 = dd * 256 + t;
                float dop = (d2 < DD) ? h[b * DD + d2] : c[b * DD + d2 - DD];
                pg += Wp[D2 + d2] * dop;
            }
#pragma unroll
            for (int dd = 0; dd < 2; dd++) {
                int d2 = dd * 256 + t;
                pg += Wp[2048 + d2] * dinp[b * DD + d2];
            }
            float4 sc4 = ((const float4*)g_scores)[b * 256 + t];
            int4   id4 = ((const int4*)src)[b * 256 + t];
            float4 a4;
            a4.x = (id4.x != 0) ? __expf(sc4.x - M) * invZ : 0.f;
            a4.y = (id4.y != 0) ? __expf(sc4.y - M) * invZ : 0.f;
            a4.z = (id4.z != 0) ? __expf(sc4.z - M) * invZ : 0.f;
            a4.w = (id4.w != 0) ? __expf(sc4.w - M) * invZ : 0.f;
            ((float4*)g_attn)[b * 256 + t] = a4;
            ((float4*)out_attn)[b * 256 + t] = a4;
        }
#pragma unroll
        for (int o = 16; o; o >>= 1) pg += __shfl_down_sync(0xffffffffu, pg, o);
        if (!(t & 31)) sred[t >> 5] = pg;
        __syncthreads();
        if (t == 0) {
            float tot = 0.f;
#pragma unroll
            for (int i = 0; i < 8; i++) tot += sred[i];
            atomicAdd(&g_pgen_acc[b], tot);
            __threadfence();
            int old = atomicAdd(&g_ctr_cb[b], 1);
            slast = (old == 3);
        }
        __syncthreads();
        if (slast && t == 0) {
            __threadfence();
            float tot = __ldcg(&g_pgen_acc[b]) + bp[0];
            g_pgen[b] = 1.f / (1.f + __expf(-tot));
        }
    }
}

// ===========================================================================
// C: k6 hidden GEMM (bids 0..95, split-K 24) + k8a vocab logits (96..479)
// ===========================================================================
#define XS6  68
#define WSTR 20
__global__ void __launch_bounds__(256, 2)
kC_hidden_logits(const float* __restrict__ Wv1, const float* __restrict__ bv1,
                 const float* __restrict__ Wv2) {
    __shared__ __align__(16) float cbuf[10880];
    __shared__ int slast;
    int t = threadIdx.x;
    int bid = blockIdx.x;

    if (bid < 96) {
        // ---- k6: 96 blocks; jb = bid&3 (128 j), kb = bid>>2 (64 k) ----
        float* sW = cbuf;
        float* sX = cbuf + 128 * XS6;
        int tj = t & 63, tb = t >> 6;
        int jb = bid & 3, kb = bid >> 2;
        int j0 = jb * 128;
        int k0s = kb * 64;
        unsigned long long acc2[2][8];
#pragma unroll
        for (int jr = 0; jr < 2; jr++)
#pragma unroll
            for (int bj = 0; bj < 8; bj++) acc2[jr][bj] = 0ull;
#pragma unroll
        for (int li = 0; li < 8; li++) {
            int flat = li * 256 + t;
            int row = flat >> 4, kc = flat & 15;
            float4 f = *(const float4*)(Wv1 + (size_t)(j0 + row) * D3 + k0s + kc * 4);
            *(float4*)(sW + row * XS6 + kc * 4) = f;
        }
#pragma unroll
        for (int li = 0; li < 2; li++) {
            int flat = li * 256 + t;
            int kk = flat >> 3, bq = flat & 7;
            float4 f = ((const float4*)g_temp_t)[(size_t)(k0s + kk) * 8 + bq];
            sX[(bq * 4 + 0) * XS6 + kk] = f.x;
            sX[(bq * 4 + 1) * XS6 + kk] = f.y;
            sX[(bq * 4 + 2) * XS6 + kk] = f.z;
            sX[(bq * 4 + 3) * XS6 + kk] = f.w;
        }
        __syncthreads();
#pragma unroll
        for (int kq = 0; kq < 16; kq++) {
            ulonglong2 xv[8];
#pragma unroll
            for (int bj = 0; bj < 8; bj++)
                xv[bj] = *(const ulonglong2*)(sX + (tb * 8 + bj) * XS6 + kq * 4);
#pragma unroll
            for (int jr = 0; jr < 2; jr++) {
                ulonglong2 wv = *(const ulonglong2*)(sW + (jr * 64 + tj) * XS6 + kq * 4);
#pragma unroll
                for (int bj = 0; bj < 8; bj++) {
                    asm("fma.rn.f32x2 %0, %1, %2, %0;"
                        : "+l"(acc2[jr][bj]) : "l"(wv.x), "l"(xv[bj].x));
                    asm("fma.rn.f32x2 %0, %1, %2, %0;"
                        : "+l"(acc2[jr][bj]) : "l"(wv.y), "l"(xv[bj].y));
                }
            }
        }
#pragma unroll
        for (int jr = 0; jr < 2; jr++)
#pragma unroll
            for (int bj = 0; bj < 8; bj++) {
                unsigned long long a = acc2[jr][bj];
                float v = __uint_as_float((unsigned)(a & 0xffffffffu)) +
                          __uint_as_float((unsigned)(a >> 32));
                g_hpart[((size_t)kb * 32 + tb * 8 + bj) * DD + j0 + jr * 64 + tj] = v;
            }
        __syncthreads();
        if (t == 0) {
            __threadfence();
            int old = atomicAdd(&g_ctr_h[jb], 1);
            slast = (old == KB6 - 1);
        }
        __syncthreads();
        if (!slast) return;
        __threadfence();
#pragma unroll
        for (int li = 0; li < 4; li++) {
            int flat = li * 256 + t;
            int b = flat >> 5, jq = flat & 31;
            float4 sum = *(const float4*)(bv1 + j0 + jq * 4);
#pragma unroll
            for (int p = 0; p < KB6; p++) {
                float4 v = __ldcg((const float4*)(g_hpart + ((size_t)p * 32 + b) * DD + j0 + jq * 4));
                sum.x += v.x; sum.y += v.y; sum.z += v.z; sum.w += v.w;
            }
            *(float4*)(g_hidden + (size_t)b * DD + j0 + jq * 4) = sum;
        }
        __threadfence();
        __syncthreads();
        if (t == 0) atomicAdd(&g_hready, 1);
        return;
    }

    // ---- k8a part ----
    float* Ws = cbuf;
    float* Hs = cbuf + 256 * WSTR;
    int idx = bid - 96;
    if (idx == 0 && t < BB) { g_sumtot[t] = 0.f; g_ctr_v[t] = 0; }
    int tv = t & 63, tb = t >> 6;
    int v0 = (idx % 192) * 256;
    int ks = idx / 192;
    int kbase = ks * 256;

    unsigned long long acc2[4][8];
#pragma unroll
    for (int j = 0; j < 4; j++)
#pragma unroll
        for (int bj = 0; bj < 8; bj++) acc2[j][bj] = 0ull;

    float4 wreg[4];
    float  hreg0, hreg1;
    {
        int k0 = kbase;
#pragma unroll
        for (int li = 0; li < 4; li++) {
            int flat = li * 256 + t;
            int v = flat >> 2, kq = flat & 3;
            int gv = v0 + v;
            wreg[li] = (gv < VV)
                ? __ldcs((const float4*)(Wv2 + (size_t)gv * DD + k0 + kq * 4))
                : make_float4(0.f, 0.f, 0.f, 0.f);
        }
#pragma unroll
        for (int li = 0; li < 4; li++) {
            int flat = li * 256 + t;
            int v = flat >> 2, kq = flat & 3;
            *(float4*)(Ws + v * WSTR + kq * 4) = wreg[li];
        }
    }
    // prefetch W tiles 1..4 into L2 while waiting for hidden
#pragma unroll
    for (int pf = 1; pf <= 4; pf++) {
        int gv = v0 + t;
        if (gv < VV)
            asm volatile("prefetch.global.L2 [%0];"
                         :: "l"(Wv2 + (size_t)gv * DD + kbase + pf * 16));
    }
    if (t == 0) {
        while (*(volatile int*)&g_hready < JB6) __nanosleep(64);
    }
    __syncthreads();
    __threadfence();
    {
        int k0 = kbase;
        hreg0 = __ldcg(&g_hidden[((t)       >> 4) * DD + k0 + ((t)       & 15)]);
        hreg1 = __ldcg(&g_hidden[((t + 256) >> 4) * DD + k0 + ((t + 256) & 15)]);
        Hs[t] = hreg0;
        Hs[t + 256] = hreg1;
    }
    __syncthreads();

    for (int tile = 0; tile < 16; tile++) {
        if (tile < 15) {
            int k0 = kbase + (tile + 1) * 16;
#pragma unroll
            for (int li = 0; li < 4; li++) {
                int flat = li * 256 + t;
                int v = flat >> 2, kq = flat & 3;
                int gv = v0 + v;
                wreg[li] = (gv < VV)
                    ? __ldcs((const float4*)(Wv2 + (size_t)gv * DD + k0 + kq * 4))
                    : make_float4(0.f, 0.f, 0.f, 0.f);
            }
            hreg0 = g_hidden[((t)       >> 4) * DD + k0 + ((t)       & 15)];
            hreg1 = g_hidden[((t + 256) >> 4) * DD + k0 + ((t + 256) & 15)];
        }
#pragma unroll
        for (int kq = 0; kq < 4; kq++) {
            ulonglong2 h2[8];
#pragma unroll
            for (int bj = 0; bj < 8; bj++)
                h2[bj] = *(const ulonglong2*)(Hs + (tb * 8 + bj) * 16 + kq * 4);
#pragma unroll
            for (int j = 0; j < 4; j++) {
                ulonglong2 w2 = *(const ulonglong2*)(Ws + (tv + 64 * j) * WSTR + kq * 4);
#pragma unroll
                for (int bj = 0; bj < 8; bj++) {
                    asm("fma.rn.f32x2 %0, %1, %2, %0;"
                        : "+l"(acc2[j][bj]) : "l"(w2.x), "l"(h2[bj].x));
                    asm("fma.rn.f32x2 %0, %1, %2, %0;"
                        : "+l"(acc2[j][bj]) : "l"(w2.y), "l"(h2[bj].y));
                }
            }
        }
        if (tile < 15) {
            __syncthreads();
#pragma unroll
            for (int li = 0; li < 4; li++) {
                int flat = li * 256 + t;
                int v = flat >> 2, kq = flat & 3;
                *(float4*)(Ws + v * WSTR + kq * 4) = wreg[li];
            }
            Hs[t] = hreg0;
            Hs[t + 256] = hreg1;
            __syncthreads();
        }
    }
    float accf[4][8];
#pragma unroll
    for (int j = 0; j < 4; j++)
#pragma unroll
        for (int bj = 0; bj < 8; bj++) {
            unsigned long long a = acc2[j][bj];
            accf[j][bj] = __uint_as_float((unsigned)(a & 0xffffffffu)) +
                          __uint_as_float((unsigned)(a >> 32));
        }
#pragma unroll
    for (int p = 0; p < 2; p++) {
        __syncthreads();
        if ((tb >> 1) == p) {
#pragma unroll
            for (int j = 0; j < 4; j++)
#pragma unroll
                for (int bj = 0; bj < 8; bj++)
                    Ws[((tb & 1) * 8 + bj) * 256 + tv + 64 * j] = accf[j][bj];
        }
        __syncthreads();
#pragma unroll
        for (int i = 0; i < 4; i++) {
            int ii = i * 256 + t;
            int row = ii >> 6, col = ii & 63;
            *(float4*)(g_lpart + ((size_t)(ks * 32 + p * 16 + row) * VP + v0 + col * 4)) =
                *(const float4*)(Ws + row * 256 + col * 4);
        }
    }
}

// ===========================================================================
// D: exp (regs) + per-b sum; local smem scatter; spin on sum counter only;
//    single-pass combine + zero-fix. Zeroes kA counters for next replay.
// ===========================================================================
__global__ void kD_exp_final(const float* __restrict__ bv2, float* __restrict__ dout,
                             const int* __restrict__ src) {
    __shared__ float ssc[2048];
    __shared__ float sm[8];
    int b = blockIdx.x, cb = blockIdx.y, t = threadIdx.x;
    if (b == 0 && cb == 0) {
        if (t == 0) { g_ctr_dec1 = 0; g_hready = 0; }
        if (t < BB) { g_ctr_c2[t] = 0; g_ctr_cb[t] = 0; g_pgen_acc[t] = 0.f; }
        if (t < 128) g_ctr_d[t] = 0;
        if (t < JB6) g_ctr_h[t] = 0;
    }
    int base = cb * 2048;
    float pg = g_pgen[b];
    float ev[8];
    float sum = 0.f;
#pragma unroll
    for (int it = 0; it < 8; it++) {
        int v = base + it * 256 + t;
        float e = 0.f;
        if (v < VV) {
            float l = g_lpart[(size_t)b * VP + v] + g_lpart[(size_t)(32 + b) * VP + v] + bv2[v];
            e = __expf(l);
            sum += e;
        }
        ev[it] = e;
    }
#pragma unroll
    for (int o = 16; o; o >>= 1) sum += __shfl_down_sync(0xffffffffu, sum, o);
    if (!(t & 31)) sm[t >> 5] = sum;
    __syncthreads();
    if (t == 0) {
        float tot = 0.f;
#pragma unroll
        for (int i = 0; i < 8; i++) tot += sm[i];
        atomicAdd(&g_sumtot[b], tot);
        __threadfence();
        atomicAdd(&g_ctr_v[b], 1);
    }
#pragma unroll
    for (int i = 0; i < 8; i++) ssc[i * 256 + t] = 0.f;
    __syncthreads();
#pragma unroll
    for (int i = 0; i < 4; i++) {
        int si = i * 256 + t;
        int idx = src[b * SS + si];
        int off = idx - base;
        if ((unsigned)off < 2048u)
            atomicAdd(&ssc[off], g_attn[b * SS + si]);
    }
    __syncthreads();
    if (t == 0) {
        while (*(volatile int*)&g_ctr_v[b] < NCB) __nanosleep(32);
    }
    __syncthreads();
    __threadfence();
    float s  = __ldcg(&g_sumtot[b]);
    float sc = pg / s;
    float f  = 1.f - pg;
#pragma unroll
    for (int it = 0; it < 8; it++) {
        int v = base + it * 256 + t;
        if (v < VF) {
            float p = ev[it] * sc + f * ssc[it * 256 + t];
            if (p == 0.f) p = 1e-12f;
            dout[(size_t)b * VF + v] = p;
        }
    }
}

extern "C" void kernel_launch(void* const* d_in, const int* in_sizes, int n_in,
                              void* d_out, int out_size) {
    const float* dec_output = (const float*)d_in[0];
    const float* hh         = (const float*)d_in[1];
    const float* cc         = (const float*)d_in[2];
    const float* dinp       = (const float*)d_in[3];
    const float* enc        = (const float*)d_in[4];
    const float* enc1       = (const float*)d_in[5];
    const int*   src        = (const int*)  d_in[6];
    const float* W_dec      = (const float*)d_in[7];
    const float* b_dec      = (const float*)d_in[8];
    const float* w_attn     = (const float*)d_in[9];
    const float* W_v1       = (const float*)d_in[10];
    const float* b_v1       = (const float*)d_in[11];
    const float* W_v2       = (const float*)d_in[12];
    const float* b_v2       = (const float*)d_in[13];
    const float* W_p        = (const float*)d_in[14];
    const float* b_p        = (const float*)d_in[15];
    const float* gam        = (const float*)d_in[16];
    const float* bet        = (const float*)d_in[17];
    const float* bn_m       = (const float*)d_in[18];
    const float* bn_v       = (const float*)d_in[19];

    float* dout     = (float*)d_out;
    float* out_attn = dout + BB * VF;
    float* out_ctx  = out_attn + BB * SS;

    kA_all<<<1664, 256>>>(hh, cc, dec_output, W_dec, b_dec,
                          (const float4*)enc1, (const float4*)w_attn,
                          (const float4*)enc, src, out_attn,
                          bn_m, bn_v, gam, bet, W_p, b_p, dinp, out_ctx);
    kC_hidden_logits<<<480, 256>>>(W_v1, b_v1, W_v2);
    kD_exp_final  <<<dim3(32, NCB), 256>>>(b_v2, dout, src);
}